// round 1
// baseline (speedup 1.0000x reference)
#include <cuda_runtime.h>
#include <cstddef>

// Problem constants
#define NB 8
#define NC 512
#define NH 64
#define NW 64
#define NCQ 64
#define HWP 4096   // NH*NW
#define KDIM 512

// Scratch (statically allocated device globals; no cudaMalloc allowed)
__device__ float g_q  [NB * NCQ * HWP];   // 8 MB
__device__ float g_k  [NB * NCQ * HWP];   // 8 MB
__device__ float g_v2 [NB * NC  * HWP];   // 64 MB
__device__ float g_v1 [NB * NC  * HWP];   // 64 MB
__device__ float g_att[NB * HWP * 128];   // 16 MB  [b,h,w, 0:64]=E_H, [64:128]=E_W

// ---------------------------------------------------------------------------
// Batched GEMM: Out[b][m][p] = sum_k W[m][k] * X[b][k][p] + bias[m]
// X is [K=512][N=4096] per batch (row-major, N contiguous).
// BN=128, TN=8 fixed; 256 threads.
// ---------------------------------------------------------------------------
template<int BM, int BK, int TM>
__global__ void gemm_wx(const float* __restrict__ Wm,
                        const float* __restrict__ bias,
                        const float* __restrict__ X,
                        float* __restrict__ Out,
                        int M)
{
    constexpr int BN = 128, TN = 8;
    constexpr int THREADS = (BM / TM) * (BN / TN);
    static_assert(THREADS == 256, "expect 256 threads");

    __shared__ float As[BK][BM + 1];
    __shared__ float Bs[BK][BN];

    const int K = KDIM, N = HWP;
    const int b  = blockIdx.z;
    const int m0 = blockIdx.y * BM;
    const int p0 = blockIdx.x * BN;
    const float* Xb = X + (size_t)b * K * N + p0;
    float* Ob = Out + (size_t)b * M * N;

    const int t  = threadIdx.x;
    const int tx = t & 15;   // BN/TN = 16 groups
    const int ty = t >> 4;   // BM/TM = 16 groups

    float acc[TM][TN];
    #pragma unroll
    for (int i = 0; i < TM; i++)
        #pragma unroll
        for (int j = 0; j < TN; j++) acc[i][j] = 0.f;

    for (int k0 = 0; k0 < K; k0 += BK) {
        // Load A tile (BM x BK), store transposed As[k][m]
        #pragma unroll
        for (int i = 0; i < (BM * BK) / THREADS; i++) {
            int idx = t + i * THREADS;
            int m = idx / BK, k = idx % BK;
            As[k][m] = Wm[(size_t)(m0 + m) * K + k0 + k];
        }
        // Load B tile (BK x BN) vectorized
        #pragma unroll
        for (int i = 0; i < (BK * BN / 4) / THREADS; i++) {
            int idx = t + i * THREADS;
            int k = idx / (BN / 4), p4 = idx % (BN / 4);
            *reinterpret_cast<float4*>(&Bs[k][p4 * 4]) =
                *reinterpret_cast<const float4*>(&Xb[(size_t)(k0 + k) * N + p4 * 4]);
        }
        __syncthreads();
        #pragma unroll
        for (int kk = 0; kk < BK; kk++) {
            float a[TM];
            #pragma unroll
            for (int i = 0; i < TM; i++) a[i] = As[kk][ty * TM + i];
            float4 b0 = *reinterpret_cast<const float4*>(&Bs[kk][tx * TN]);
            float4 b1 = *reinterpret_cast<const float4*>(&Bs[kk][tx * TN + 4]);
            float bb[TN] = {b0.x, b0.y, b0.z, b0.w, b1.x, b1.y, b1.z, b1.w};
            #pragma unroll
            for (int i = 0; i < TM; i++)
                #pragma unroll
                for (int j = 0; j < TN; j++)
                    acc[i][j] += a[i] * bb[j];
        }
        __syncthreads();
    }

    #pragma unroll
    for (int i = 0; i < TM; i++) {
        int m = m0 + ty * TM + i;
        float bv = bias[m];
        float4 o0 = {acc[i][0] + bv, acc[i][1] + bv, acc[i][2] + bv, acc[i][3] + bv};
        float4 o1 = {acc[i][4] + bv, acc[i][5] + bv, acc[i][6] + bv, acc[i][7] + bv};
        float* op = &Ob[(size_t)m * N + p0 + tx * TN];
        *reinterpret_cast<float4*>(op)     = o0;
        *reinterpret_cast<float4*>(op + 4) = o1;
    }
}

// ---------------------------------------------------------------------------
// energy_H: E[b,h,w,H'] = sum_c q[b,c,h,w] * k[b,c,H',w]   (fixed b,w)
// ---------------------------------------------------------------------------
__global__ void energy_H_kernel(const float* __restrict__ q,
                                const float* __restrict__ k,
                                float* __restrict__ att)
{
    const int w = blockIdx.x, b = blockIdx.y;
    __shared__ float Qs[64][65];
    __shared__ float Ks[64][65];
    const int t = threadIdx.x;
    #pragma unroll
    for (int i = 0; i < 16; i++) {
        int idx = t + i * 256;
        int c = idx >> 6, h = idx & 63;
        size_t g = ((size_t)(b * NCQ + c) * NH + h) * NW + w;
        Qs[c][h] = q[g];
        Ks[c][h] = k[g];
    }
    __syncthreads();
    const int tx = t & 15, ty = t >> 4;
    float acc[4][4];
    #pragma unroll
    for (int i = 0; i < 4; i++)
        #pragma unroll
        for (int j = 0; j < 4; j++) acc[i][j] = 0.f;
    for (int c = 0; c < 64; c++) {
        float qa[4], kb[4];
        #pragma unroll
        for (int i = 0; i < 4; i++) qa[i] = Qs[c][ty * 4 + i];
        #pragma unroll
        for (int j = 0; j < 4; j++) kb[j] = Ks[c][tx * 4 + j];
        #pragma unroll
        for (int i = 0; i < 4; i++)
            #pragma unroll
            for (int j = 0; j < 4; j++) acc[i][j] += qa[i] * kb[j];
    }
    #pragma unroll
    for (int i = 0; i < 4; i++) {
        int h = ty * 4 + i;
        float4 o = {acc[i][0], acc[i][1], acc[i][2], acc[i][3]};
        *reinterpret_cast<float4*>(&att[((size_t)(b * NH + h) * NW + w) * 128 + tx * 4]) = o;
    }
}

// ---------------------------------------------------------------------------
// energy_W: E[b,h,w,W'] = sum_c q[b,c,h,w] * k[b,c,h,W']   (fixed b,h)
// ---------------------------------------------------------------------------
__global__ void energy_W_kernel(const float* __restrict__ q,
                                const float* __restrict__ k,
                                float* __restrict__ att)
{
    const int h = blockIdx.x, b = blockIdx.y;
    __shared__ float Qs[64][65];
    __shared__ float Ks[64][65];
    const int t = threadIdx.x;
    #pragma unroll
    for (int i = 0; i < 16; i++) {
        int idx = t + i * 256;
        int c = idx >> 6, w = idx & 63;
        size_t g = ((size_t)(b * NCQ + c) * NH + h) * NW + w;
        Qs[c][w] = q[g];
        Ks[c][w] = k[g];
    }
    __syncthreads();
    const int tx = t & 15, ty = t >> 4;
    float acc[4][4];
    #pragma unroll
    for (int i = 0; i < 4; i++)
        #pragma unroll
        for (int j = 0; j < 4; j++) acc[i][j] = 0.f;
    for (int c = 0; c < 64; c++) {
        float qa[4], kb[4];
        #pragma unroll
        for (int i = 0; i < 4; i++) qa[i] = Qs[c][ty * 4 + i];
        #pragma unroll
        for (int j = 0; j < 4; j++) kb[j] = Ks[c][tx * 4 + j];
        #pragma unroll
        for (int i = 0; i < 4; i++)
            #pragma unroll
            for (int j = 0; j < 4; j++) acc[i][j] += qa[i] * kb[j];
    }
    #pragma unroll
    for (int i = 0; i < 4; i++) {
        int w = ty * 4 + i;
        float4 o = {acc[i][0], acc[i][1], acc[i][2], acc[i][3]};
        *reinterpret_cast<float4*>(&att[((size_t)(b * NH + h) * NW + w) * 128 + 64 + tx * 4]) = o;
    }
}

// ---------------------------------------------------------------------------
// softmax over the 128-wide concat axis; one warp per (b,h,w) row
// ---------------------------------------------------------------------------
__global__ void softmax_kernel(float* __restrict__ att)
{
    int gwarp = (blockIdx.x * blockDim.x + threadIdx.x) >> 5;
    int lane  = threadIdx.x & 31;
    if (gwarp >= NB * HWP) return;
    float4* row = reinterpret_cast<float4*>(att) + (size_t)gwarp * 32;
    float4 v = row[lane];
    float m = fmaxf(fmaxf(v.x, v.y), fmaxf(v.z, v.w));
    #pragma unroll
    for (int o = 16; o > 0; o >>= 1) m = fmaxf(m, __shfl_xor_sync(0xFFFFFFFFu, m, o));
    v.x = __expf(v.x - m); v.y = __expf(v.y - m);
    v.z = __expf(v.z - m); v.w = __expf(v.w - m);
    float s = v.x + v.y + v.z + v.w;
    #pragma unroll
    for (int o = 16; o > 0; o >>= 1) s += __shfl_xor_sync(0xFFFFFFFFu, s, o);
    float r = 1.0f / s;
    v.x *= r; v.y *= r; v.z *= r; v.w *= r;
    row[lane] = v;
}

// ---------------------------------------------------------------------------
// Pass A (H-aggregation + residual):
//   y[b,c,h,w] = x[b,c,h,w] + g * sum_H' v[b,c,H',w] * att[b,h,w,H']
// Block: fixed (b, w, c-chunk of 64); both value streams share the att tile.
// ---------------------------------------------------------------------------
__global__ void aggH_kernel(const float* __restrict__ v2,
                            const float* __restrict__ v1,
                            const float* __restrict__ x2,
                            const float* __restrict__ x1,
                            const float* __restrict__ att,
                            const float* __restrict__ gamma,
                            float* __restrict__ y)
{
    const int w  = blockIdx.x;
    const int c0 = blockIdx.y * 64;
    const int b  = blockIdx.z;
    const float g = gamma[0];
    __shared__ float As[64][65];   // As[h][H']
    __shared__ float Vs[64][65];   // Vs[c][H']
    const int t = threadIdx.x;
    #pragma unroll
    for (int i = 0; i < 16; i++) {
        int idx = t + i * 256;
        int h = idx >> 6, Hp = idx & 63;
        As[h][Hp] = att[((size_t)(b * NH + h) * NW + w) * 128 + Hp];
    }
    const float* vsrc[2] = {v2, v1};
    const float* xsrc[2] = {x2, x1};
    float* ydst[2] = {y, y + (size_t)NB * NC * HWP};
    const int tx = t & 15, ty = t >> 4;

    for (int s = 0; s < 2; s++) {
        __syncthreads();   // att ready (s=0) / previous compute done (s=1)
        #pragma unroll
        for (int i = 0; i < 16; i++) {
            int idx = t + i * 256;
            int c = idx >> 6, Hp = idx & 63;
            Vs[c][Hp] = vsrc[s][((size_t)(b * NC + c0 + c) * NH + Hp) * NW + w];
        }
        __syncthreads();
        float acc[4][4];
        #pragma unroll
        for (int i = 0; i < 4; i++)
            #pragma unroll
            for (int j = 0; j < 4; j++) acc[i][j] = 0.f;
        #pragma unroll 4
        for (int Hp = 0; Hp < 64; Hp++) {
            float a[4], bb[4];
            #pragma unroll
            for (int i = 0; i < 4; i++) a[i] = Vs[ty * 4 + i][Hp];
            #pragma unroll
            for (int j = 0; j < 4; j++) bb[j] = As[tx * 4 + j][Hp];
            #pragma unroll
            for (int i = 0; i < 4; i++)
                #pragma unroll
                for (int j = 0; j < 4; j++) acc[i][j] += a[i] * bb[j];
        }
        #pragma unroll
        for (int i = 0; i < 4; i++) {
            int c = c0 + ty * 4 + i;
            #pragma unroll
            for (int j = 0; j < 4; j++) {
                int h = tx * 4 + j;
                size_t o = ((size_t)(b * NC + c) * NH + h) * NW + w;
                ydst[s][o] = xsrc[s][o] + g * acc[i][j];
            }
        }
    }
}

// ---------------------------------------------------------------------------
// Pass B (W-aggregation, accumulate into y):
//   y[b,c,h,w] += g * sum_W' v[b,c,h,W'] * att[b,h,w,64+W']
// Block: fixed (b, h, c-chunk of 64). Fully coalesced.
// ---------------------------------------------------------------------------
__global__ void aggW_kernel(const float* __restrict__ v2,
                            const float* __restrict__ v1,
                            const float* __restrict__ att,
                            const float* __restrict__ gamma,
                            float* __restrict__ y)
{
    const int h  = blockIdx.x;
    const int c0 = blockIdx.y * 64;
    const int b  = blockIdx.z;
    const float g = gamma[0];
    __shared__ float As[64][65];   // As[w][W']
    __shared__ float Vs[64][65];   // Vs[c][W']
    const int t = threadIdx.x;
    #pragma unroll
    for (int i = 0; i < 16; i++) {
        int idx = t + i * 256;
        int w = idx >> 6, Wp = idx & 63;
        As[w][Wp] = att[((size_t)(b * NH + h) * NW + w) * 128 + 64 + Wp];
    }
    const float* vsrc[2] = {v2, v1};
    float* ydst[2] = {y, y + (size_t)NB * NC * HWP};
    const int tx = t & 15, ty = t >> 4;

    for (int s = 0; s < 2; s++) {
        __syncthreads();
        #pragma unroll
        for (int i = 0; i < 16; i++) {
            int idx = t + i * 256;
            int c = idx >> 6, Wp = idx & 63;
            Vs[c][Wp] = vsrc[s][((size_t)(b * NC + c0 + c) * NH + h) * NW + Wp];
        }
        __syncthreads();
        float acc[4][4];
        #pragma unroll
        for (int i = 0; i < 4; i++)
            #pragma unroll
            for (int j = 0; j < 4; j++) acc[i][j] = 0.f;
        #pragma unroll 4
        for (int Wp = 0; Wp < 64; Wp++) {
            float a[4], bb[4];
            #pragma unroll
            for (int i = 0; i < 4; i++) a[i] = Vs[ty * 4 + i][Wp];
            #pragma unroll
            for (int j = 0; j < 4; j++) bb[j] = As[tx * 4 + j][Wp];
            #pragma unroll
            for (int i = 0; i < 4; i++)
                #pragma unroll
                for (int j = 0; j < 4; j++) acc[i][j] += a[i] * bb[j];
        }
        #pragma unroll
        for (int i = 0; i < 4; i++) {
            int c = c0 + ty * 4 + i;
            float* yp = &ydst[s][((size_t)(b * NC + c) * NH + h) * NW + tx * 4];
            float4 cur = *reinterpret_cast<float4*>(yp);
            cur.x += g * acc[i][0];
            cur.y += g * acc[i][1];
            cur.z += g * acc[i][2];
            cur.w += g * acc[i][3];
            *reinterpret_cast<float4*>(yp) = cur;
        }
    }
}

// ---------------------------------------------------------------------------
extern "C" void kernel_launch(void* const* d_in, const int* in_sizes, int n_in,
                              void* d_out, int out_size)
{
    const float* x2    = (const float*)d_in[0];
    const float* x1    = (const float*)d_in[1];
    const float* q_w   = (const float*)d_in[2];
    const float* q_b   = (const float*)d_in[3];
    const float* k_w   = (const float*)d_in[4];
    const float* k_b   = (const float*)d_in[5];
    const float* v_w   = (const float*)d_in[6];
    const float* v_b   = (const float*)d_in[7];
    const float* gamma = (const float*)d_in[8];
    float* y = (float*)d_out;

    float *gq, *gk, *gv2, *gv1, *gatt;
    cudaGetSymbolAddress((void**)&gq,  g_q);
    cudaGetSymbolAddress((void**)&gk,  g_k);
    cudaGetSymbolAddress((void**)&gv2, g_v2);
    cudaGetSymbolAddress((void**)&gv1, g_v1);
    cudaGetSymbolAddress((void**)&gatt, g_att);

    // Projections
    gemm_wx<64, 16, 4><<<dim3(32, 1, NB), 256>>>(q_w, q_b, x2, gq, NCQ);
    gemm_wx<64, 16, 4><<<dim3(32, 1, NB), 256>>>(k_w, k_b, x2, gk, NCQ);
    gemm_wx<128, 8, 8><<<dim3(32, 4, NB), 256>>>(v_w, v_b, x2, gv2, NC);
    gemm_wx<128, 8, 8><<<dim3(32, 4, NB), 256>>>(v_w, v_b, x1, gv1, NC);

    // Energies + softmax
    energy_H_kernel<<<dim3(NW, NB), 256>>>(gq, gk, gatt);
    energy_W_kernel<<<dim3(NH, NB), 256>>>(gq, gk, gatt);
    softmax_kernel<<<(NB * HWP) / 8, 256>>>(gatt);

    // Aggregation + residual
    aggH_kernel<<<dim3(NW, 8, NB), 256>>>(gv2, gv1, x2, x1, gatt, gamma, y);
    aggW_kernel<<<dim3(NH, 8, NB), 256>>>(gv2, gv1, gatt, gamma, y);
}

// round 2
// speedup vs baseline: 1.6501x; 1.6501x over previous
#include <cuda_runtime.h>
#include <cstddef>
#include <cstdint>

// Problem constants
#define NB 8
#define NC 512
#define NH 64
#define NW 64
#define NCQ 64
#define HWP 4096   // NH*NW
#define KDIM 512

// Scratch (statically allocated device globals; no cudaMalloc allowed)
__device__ float g_q  [NB * NCQ * HWP];   // 8 MB
__device__ float g_k  [NB * NCQ * HWP];   // 8 MB
__device__ float g_v2 [NB * NC  * HWP];   // 64 MB
__device__ float g_v1 [NB * NC  * HWP];   // 64 MB
__device__ float g_att[NB * HWP * 128];   // 16 MB  [b,h,w, 0:64]=E_H, [64:128]=E_W

// ---------------------------------------------------------------------------
// tf32 tensor-core GEMM for the 1x1-conv projections.
//   Out[b][m][p] = sum_k W[m][k] * X[b][k][p] + bias[m]
// Tiles: BM=128, BN=128, BK=16, 256 threads (8 warps: 4(m) x 2(n)),
// warp tile 32x64, mma.sync.m16n8k8.tf32, double-buffered smem.
// MODE 0: v-projection pair. grid z = s*8+b (s: 0->x2/gv2, 1->x1/gv1), W=v_w.
// MODE 1: fused q+k. M=128 combined: rows 0-63 from Wq->Oq, 64-127 Wk->Ok.
// ---------------------------------------------------------------------------
__device__ __forceinline__ uint32_t f2tf32(float f) {
    uint32_t u;
    asm("cvt.rna.tf32.f32 %0, %1;" : "=r"(u) : "f"(f));
    return u;
}

template<int MODE>
__global__ void __launch_bounds__(256)
gemm_tf32(const float* __restrict__ W0, const float* __restrict__ bias0,
          const float* __restrict__ W1, const float* __restrict__ bias1,
          const float* __restrict__ X0, const float* __restrict__ X1,
          float* __restrict__ O0, float* __restrict__ O1)
{
    constexpr int BM = 128, BN = 128, BK = 16;
    constexpr int NKT = KDIM / BK;          // 32 k-tiles

    __shared__ uint32_t As[2][BK][BM + 4];  // [k][m] transposed
    __shared__ uint32_t Bs[2][BK][BN + 8];  // [k][n]

    const int t = threadIdx.x;
    const int z = blockIdx.z;
    const int b = (MODE == 0) ? (z & 7) : z;
    const int s = (MODE == 0) ? (z >> 3) : 0;
    const int m0 = (MODE == 0) ? blockIdx.y * BM : 0;
    const int n0 = blockIdx.x * BN;

    const float* Xb = ((MODE == 0 && s == 1) ? X1 : X0) + (size_t)b * KDIM * HWP + n0;

    const int warp = t >> 5, lane = t & 31;
    const int gid = lane >> 2, tig = lane & 3;
    const int wm = warp >> 1;   // 0..3
    const int wn = warp & 1;    // 0..1

    float acc[2][8][4];
    #pragma unroll
    for (int mi = 0; mi < 2; mi++)
        #pragma unroll
        for (int ni = 0; ni < 8; ni++)
            #pragma unroll
            for (int r = 0; r < 4; r++) acc[mi][ni][r] = 0.f;

    // per-thread load coordinates
    // A tile: 128 rows x 4 float4 (k). f4 id fa = t + i*256: row=fa>>2, c4=fa&3
    // B tile: 16 k-rows x 32 float4. fb = t + i*256: krow=fb>>5, c4=fb&31
    float4 pa[2], pb[2];

    auto load_global = [&](int kt) {
        const int k0 = kt * BK;
        #pragma unroll
        for (int i = 0; i < 2; i++) {
            int fa = t + i * 256;
            int row = fa >> 2, c4 = fa & 3;
            const float* src;
            if (MODE == 1) {
                src = (row < 64) ? (W0 + (size_t)row * KDIM)
                                 : (W1 + (size_t)(row - 64) * KDIM);
            } else {
                src = W0 + (size_t)(m0 + row) * KDIM;
            }
            pa[i] = *reinterpret_cast<const float4*>(src + k0 + c4 * 4);
            int fb = t + i * 256;
            int krow = fb >> 5, c4b = fb & 31;
            pb[i] = *reinterpret_cast<const float4*>(Xb + (size_t)(k0 + krow) * HWP + c4b * 4);
        }
    };
    auto store_smem = [&](int buf) {
        #pragma unroll
        for (int i = 0; i < 2; i++) {
            int fa = t + i * 256;
            int row = fa >> 2, c4 = fa & 3;
            As[buf][c4 * 4 + 0][row] = f2tf32(pa[i].x);
            As[buf][c4 * 4 + 1][row] = f2tf32(pa[i].y);
            As[buf][c4 * 4 + 2][row] = f2tf32(pa[i].z);
            As[buf][c4 * 4 + 3][row] = f2tf32(pa[i].w);
            int fb = t + i * 256;
            int krow = fb >> 5, c4b = fb & 31;
            uint4 u = {f2tf32(pb[i].x), f2tf32(pb[i].y), f2tf32(pb[i].z), f2tf32(pb[i].w)};
            *reinterpret_cast<uint4*>(&Bs[buf][krow][c4b * 4]) = u;
        }
    };

    load_global(0);
    store_smem(0);
    __syncthreads();

    for (int kt = 0; kt < NKT; kt++) {
        const int cur = kt & 1;
        if (kt + 1 < NKT) load_global(kt + 1);

        #pragma unroll
        for (int ks = 0; ks < 2; ks++) {
            const int kb = ks * 8;
            uint32_t af[2][4];
            #pragma unroll
            for (int mi = 0; mi < 2; mi++) {
                int m = wm * 32 + mi * 16;
                af[mi][0] = As[cur][kb + tig    ][m + gid];
                af[mi][1] = As[cur][kb + tig    ][m + gid + 8];
                af[mi][2] = As[cur][kb + tig + 4][m + gid];
                af[mi][3] = As[cur][kb + tig + 4][m + gid + 8];
            }
            #pragma unroll
            for (int ni = 0; ni < 8; ni++) {
                int n = wn * 64 + ni * 8 + gid;
                uint32_t b0 = Bs[cur][kb + tig    ][n];
                uint32_t b1 = Bs[cur][kb + tig + 4][n];
                #pragma unroll
                for (int mi = 0; mi < 2; mi++) {
                    asm volatile(
                        "mma.sync.aligned.m16n8k8.row.col.f32.tf32.tf32.f32 "
                        "{%0,%1,%2,%3}, {%4,%5,%6,%7}, {%8,%9}, {%0,%1,%2,%3};"
                        : "+f"(acc[mi][ni][0]), "+f"(acc[mi][ni][1]),
                          "+f"(acc[mi][ni][2]), "+f"(acc[mi][ni][3])
                        : "r"(af[mi][0]), "r"(af[mi][1]), "r"(af[mi][2]), "r"(af[mi][3]),
                          "r"(b0), "r"(b1));
                }
            }
        }

        if (kt + 1 < NKT) store_smem((kt + 1) & 1);
        __syncthreads();
    }

    // Epilogue
    #pragma unroll
    for (int mi = 0; mi < 2; mi++) {
        int ml = wm * 32 + mi * 16 + gid;    // local rows ml, ml+8
        #pragma unroll
        for (int half = 0; half < 2; half++) {
            int m = m0 + ml + half * 8;
            float bv;
            float* obase;
            if (MODE == 1) {
                if (m < 64) { bv = bias0[m];      obase = O0 + ((size_t)b * 64 + m)       * HWP; }
                else        { bv = bias1[m - 64]; obase = O1 + ((size_t)b * 64 + (m - 64)) * HWP; }
            } else {
                bv = bias0[m];
                float* O = (s == 1) ? O1 : O0;
                obase = O + ((size_t)b * NC + m) * HWP;
            }
            #pragma unroll
            for (int ni = 0; ni < 8; ni++) {
                int n = n0 + wn * 64 + ni * 8 + tig * 2;
                float2 o;
                o.x = acc[mi][ni][half * 2 + 0] + bv;
                o.y = acc[mi][ni][half * 2 + 1] + bv;
                *reinterpret_cast<float2*>(obase + n) = o;
            }
        }
    }
}

// ---------------------------------------------------------------------------
// energy_H: E[b,h,w,H'] = sum_c q[b,c,h,w] * k[b,c,H',w]   (fixed b,w)
// ---------------------------------------------------------------------------
__global__ void energy_H_kernel(const float* __restrict__ q,
                                const float* __restrict__ k,
                                float* __restrict__ att)
{
    const int w = blockIdx.x, b = blockIdx.y;
    __shared__ float Qs[64][65];
    __shared__ float Ks[64][65];
    const int t = threadIdx.x;
    #pragma unroll
    for (int i = 0; i < 16; i++) {
        int idx = t + i * 256;
        int c = idx >> 6, h = idx & 63;
        size_t g = ((size_t)(b * NCQ + c) * NH + h) * NW + w;
        Qs[c][h] = q[g];
        Ks[c][h] = k[g];
    }
    __syncthreads();
    const int tx = t & 15, ty = t >> 4;
    float acc[4][4];
    #pragma unroll
    for (int i = 0; i < 4; i++)
        #pragma unroll
        for (int j = 0; j < 4; j++) acc[i][j] = 0.f;
    for (int c = 0; c < 64; c++) {
        float qa[4], kb[4];
        #pragma unroll
        for (int i = 0; i < 4; i++) qa[i] = Qs[c][ty * 4 + i];
        #pragma unroll
        for (int j = 0; j < 4; j++) kb[j] = Ks[c][tx * 4 + j];
        #pragma unroll
        for (int i = 0; i < 4; i++)
            #pragma unroll
            for (int j = 0; j < 4; j++) acc[i][j] += qa[i] * kb[j];
    }
    #pragma unroll
    for (int i = 0; i < 4; i++) {
        int h = ty * 4 + i;
        float4 o = {acc[i][0], acc[i][1], acc[i][2], acc[i][3]};
        *reinterpret_cast<float4*>(&att[((size_t)(b * NH + h) * NW + w) * 128 + tx * 4]) = o;
    }
}

// ---------------------------------------------------------------------------
// energy_W: E[b,h,w,W'] = sum_c q[b,c,h,w] * k[b,c,h,W']   (fixed b,h)
// ---------------------------------------------------------------------------
__global__ void energy_W_kernel(const float* __restrict__ q,
                                const float* __restrict__ k,
                                float* __restrict__ att)
{
    const int h = blockIdx.x, b = blockIdx.y;
    __shared__ float Qs[64][65];
    __shared__ float Ks[64][65];
    const int t = threadIdx.x;
    #pragma unroll
    for (int i = 0; i < 16; i++) {
        int idx = t + i * 256;
        int c = idx >> 6, w = idx & 63;
        size_t g = ((size_t)(b * NCQ + c) * NH + h) * NW + w;
        Qs[c][w] = q[g];
        Ks[c][w] = k[g];
    }
    __syncthreads();
    const int tx = t & 15, ty = t >> 4;
    float acc[4][4];
    #pragma unroll
    for (int i = 0; i < 4; i++)
        #pragma unroll
        for (int j = 0; j < 4; j++) acc[i][j] = 0.f;
    for (int c = 0; c < 64; c++) {
        float qa[4], kb[4];
        #pragma unroll
        for (int i = 0; i < 4; i++) qa[i] = Qs[c][ty * 4 + i];
        #pragma unroll
        for (int j = 0; j < 4; j++) kb[j] = Ks[c][tx * 4 + j];
        #pragma unroll
        for (int i = 0; i < 4; i++)
            #pragma unroll
            for (int j = 0; j < 4; j++) acc[i][j] += qa[i] * kb[j];
    }
    #pragma unroll
    for (int i = 0; i < 4; i++) {
        int w = ty * 4 + i;
        float4 o = {acc[i][0], acc[i][1], acc[i][2], acc[i][3]};
        *reinterpret_cast<float4*>(&att[((size_t)(b * NH + h) * NW + w) * 128 + 64 + tx * 4]) = o;
    }
}

// ---------------------------------------------------------------------------
// softmax over the 128-wide concat axis; one warp per (b,h,w) row
// ---------------------------------------------------------------------------
__global__ void softmax_kernel(float* __restrict__ att)
{
    int gwarp = (blockIdx.x * blockDim.x + threadIdx.x) >> 5;
    int lane  = threadIdx.x & 31;
    if (gwarp >= NB * HWP) return;
    float4* row = reinterpret_cast<float4*>(att) + (size_t)gwarp * 32;
    float4 v = row[lane];
    float m = fmaxf(fmaxf(v.x, v.y), fmaxf(v.z, v.w));
    #pragma unroll
    for (int o = 16; o > 0; o >>= 1) m = fmaxf(m, __shfl_xor_sync(0xFFFFFFFFu, m, o));
    v.x = __expf(v.x - m); v.y = __expf(v.y - m);
    v.z = __expf(v.z - m); v.w = __expf(v.w - m);
    float s = v.x + v.y + v.z + v.w;
    #pragma unroll
    for (int o = 16; o > 0; o >>= 1) s += __shfl_xor_sync(0xFFFFFFFFu, s, o);
    float r = 1.0f / s;
    v.x *= r; v.y *= r; v.z *= r; v.w *= r;
    row[lane] = v;
}

// ---------------------------------------------------------------------------
// Pass A (H-aggregation + residual):
//   y[b,c,h,w] = x[b,c,h,w] + g * sum_H' v[b,c,H',w] * att[b,h,w,H']
// ---------------------------------------------------------------------------
__global__ void aggH_kernel(const float* __restrict__ v2,
                            const float* __restrict__ v1,
                            const float* __restrict__ x2,
                            const float* __restrict__ x1,
                            const float* __restrict__ att,
                            const float* __restrict__ gamma,
                            float* __restrict__ y)
{
    const int w  = blockIdx.x;
    const int c0 = blockIdx.y * 64;
    const int b  = blockIdx.z;
    const float g = gamma[0];
    __shared__ float As[64][65];   // As[h][H']
    __shared__ float Vs[64][65];   // Vs[c][H']
    const int t = threadIdx.x;
    #pragma unroll
    for (int i = 0; i < 16; i++) {
        int idx = t + i * 256;
        int h = idx >> 6, Hp = idx & 63;
        As[h][Hp] = att[((size_t)(b * NH + h) * NW + w) * 128 + Hp];
    }
    const float* vsrc[2] = {v2, v1};
    const float* xsrc[2] = {x2, x1};
    float* ydst[2] = {y, y + (size_t)NB * NC * HWP};
    const int tx = t & 15, ty = t >> 4;

    for (int s = 0; s < 2; s++) {
        __syncthreads();
        #pragma unroll
        for (int i = 0; i < 16; i++) {
            int idx = t + i * 256;
            int c = idx >> 6, Hp = idx & 63;
            Vs[c][Hp] = vsrc[s][((size_t)(b * NC + c0 + c) * NH + Hp) * NW + w];
        }
        __syncthreads();
        float acc[4][4];
        #pragma unroll
        for (int i = 0; i < 4; i++)
            #pragma unroll
            for (int j = 0; j < 4; j++) acc[i][j] = 0.f;
        #pragma unroll 4
        for (int Hp = 0; Hp < 64; Hp++) {
            float a[4], bb[4];
            #pragma unroll
            for (int i = 0; i < 4; i++) a[i] = Vs[ty * 4 + i][Hp];
            #pragma unroll
            for (int j = 0; j < 4; j++) bb[j] = As[tx * 4 + j][Hp];
            #pragma unroll
            for (int i = 0; i < 4; i++)
                #pragma unroll
                for (int j = 0; j < 4; j++) acc[i][j] += a[i] * bb[j];
        }
        #pragma unroll
        for (int i = 0; i < 4; i++) {
            int c = c0 + ty * 4 + i;
            #pragma unroll
            for (int j = 0; j < 4; j++) {
                int h = tx * 4 + j;
                size_t o = ((size_t)(b * NC + c) * NH + h) * NW + w;
                ydst[s][o] = xsrc[s][o] + g * acc[i][j];
            }
        }
    }
}

// ---------------------------------------------------------------------------
// Pass B (W-aggregation, accumulate into y):
//   y[b,c,h,w] += g * sum_W' v[b,c,h,W'] * att[b,h,w,64+W']
// ---------------------------------------------------------------------------
__global__ void aggW_kernel(const float* __restrict__ v2,
                            const float* __restrict__ v1,
                            const float* __restrict__ att,
                            const float* __restrict__ gamma,
                            float* __restrict__ y)
{
    const int h  = blockIdx.x;
    const int c0 = blockIdx.y * 64;
    const int b  = blockIdx.z;
    const float g = gamma[0];
    __shared__ float As[64][65];   // As[w][W']
    __shared__ float Vs[64][65];   // Vs[c][W']
    const int t = threadIdx.x;
    #pragma unroll
    for (int i = 0; i < 16; i++) {
        int idx = t + i * 256;
        int w = idx >> 6, Wp = idx & 63;
        As[w][Wp] = att[((size_t)(b * NH + h) * NW + w) * 128 + 64 + Wp];
    }
    const float* vsrc[2] = {v2, v1};
    float* ydst[2] = {y, y + (size_t)NB * NC * HWP};
    const int tx = t & 15, ty = t >> 4;

    for (int s = 0; s < 2; s++) {
        __syncthreads();
        #pragma unroll
        for (int i = 0; i < 16; i++) {
            int idx = t + i * 256;
            int c = idx >> 6, Wp = idx & 63;
            Vs[c][Wp] = vsrc[s][((size_t)(b * NC + c0 + c) * NH + h) * NW + Wp];
        }
        __syncthreads();
        float acc[4][4];
        #pragma unroll
        for (int i = 0; i < 4; i++)
            #pragma unroll
            for (int j = 0; j < 4; j++) acc[i][j] = 0.f;
        #pragma unroll 4
        for (int Wp = 0; Wp < 64; Wp++) {
            float a[4], bb[4];
            #pragma unroll
            for (int i = 0; i < 4; i++) a[i] = Vs[ty * 4 + i][Wp];
            #pragma unroll
            for (int j = 0; j < 4; j++) bb[j] = As[tx * 4 + j][Wp];
            #pragma unroll
            for (int i = 0; i < 4; i++)
                #pragma unroll
                for (int j = 0; j < 4; j++) acc[i][j] += a[i] * bb[j];
        }
        #pragma unroll
        for (int i = 0; i < 4; i++) {
            int c = c0 + ty * 4 + i;
            float* yp = &ydst[s][((size_t)(b * NC + c) * NH + h) * NW + tx * 4];
            float4 cur = *reinterpret_cast<float4*>(yp);
            cur.x += g * acc[i][0];
            cur.y += g * acc[i][1];
            cur.z += g * acc[i][2];
            cur.w += g * acc[i][3];
            *reinterpret_cast<float4*>(yp) = cur;
        }
    }
}

// ---------------------------------------------------------------------------
extern "C" void kernel_launch(void* const* d_in, const int* in_sizes, int n_in,
                              void* d_out, int out_size)
{
    const float* x2    = (const float*)d_in[0];
    const float* x1    = (const float*)d_in[1];
    const float* q_w   = (const float*)d_in[2];
    const float* q_b   = (const float*)d_in[3];
    const float* k_w   = (const float*)d_in[4];
    const float* k_b   = (const float*)d_in[5];
    const float* v_w   = (const float*)d_in[6];
    const float* v_b   = (const float*)d_in[7];
    const float* gamma = (const float*)d_in[8];
    float* y = (float*)d_out;

    float *gq, *gk, *gv2, *gv1, *gatt;
    cudaGetSymbolAddress((void**)&gq,  g_q);
    cudaGetSymbolAddress((void**)&gk,  g_k);
    cudaGetSymbolAddress((void**)&gv2, g_v2);
    cudaGetSymbolAddress((void**)&gv1, g_v1);
    cudaGetSymbolAddress((void**)&gatt, g_att);

    // Projections (tf32 tensor cores)
    gemm_tf32<0><<<dim3(32, 4, 16), 256>>>(v_w, v_b, nullptr, nullptr, x2, x1, gv2, gv1);
    gemm_tf32<1><<<dim3(32, 1, 8),  256>>>(q_w, q_b, k_w, k_b, x2, nullptr, gq, gk);

    // Energies + softmax
    energy_H_kernel<<<dim3(NW, NB), 256>>>(gq, gk, gatt);
    energy_W_kernel<<<dim3(NH, NB), 256>>>(gq, gk, gatt);
    softmax_kernel<<<(NB * HWP) / 8, 256>>>(gatt);

    // Aggregation + residual
    aggH_kernel<<<dim3(NW, 8, NB), 256>>>(gv2, gv1, x2, x1, gatt, gamma, y);
    aggW_kernel<<<dim3(NH, 8, NB), 256>>>(gv2, gv1, gatt, gamma, y);
}

// round 3
// speedup vs baseline: 2.5949x; 1.5726x over previous
#include <cuda_runtime.h>
#include <cstddef>
#include <cstdint>

// Problem constants
#define NB 8
#define NC 512
#define NH 64
#define NW 64
#define NCQ 64
#define HWP 4096   // NH*NW
#define KDIM 512

// Scratch (statically allocated device globals; no cudaMalloc allowed)
__device__ float g_q  [NB * NCQ * HWP];   // 8 MB
__device__ float g_k  [NB * NCQ * HWP];   // 8 MB
__device__ float g_v2 [NB * NC  * HWP];   // 64 MB
__device__ float g_v1 [NB * NC  * HWP];   // 64 MB
__device__ float g_att[NB * HWP * 128];   // 16 MB  [b,h,w, 0:64]=E_H, [64:128]=E_W

__device__ __forceinline__ uint32_t f2tf32(float f) {
    uint32_t u;
    asm("cvt.rna.tf32.f32 %0, %1;" : "=r"(u) : "f"(f));
    return u;
}

__device__ __forceinline__ void mma_tf32(float& d0, float& d1, float& d2, float& d3,
                                         uint32_t a0, uint32_t a1, uint32_t a2, uint32_t a3,
                                         uint32_t b0, uint32_t b1) {
    asm volatile(
        "mma.sync.aligned.m16n8k8.row.col.f32.tf32.tf32.f32 "
        "{%0,%1,%2,%3}, {%4,%5,%6,%7}, {%8,%9}, {%0,%1,%2,%3};"
        : "+f"(d0), "+f"(d1), "+f"(d2), "+f"(d3)
        : "r"(a0), "r"(a1), "r"(a2), "r"(a3), "r"(b0), "r"(b1));
}

// ---------------------------------------------------------------------------
// tf32 tensor-core GEMM for the 1x1-conv projections (unchanged from R2).
// ---------------------------------------------------------------------------
template<int MODE>
__global__ void __launch_bounds__(256)
gemm_tf32(const float* __restrict__ W0, const float* __restrict__ bias0,
          const float* __restrict__ W1, const float* __restrict__ bias1,
          const float* __restrict__ X0, const float* __restrict__ X1,
          float* __restrict__ O0, float* __restrict__ O1)
{
    constexpr int BM = 128, BN = 128, BK = 16;
    constexpr int NKT = KDIM / BK;

    __shared__ uint32_t As[2][BK][BM + 4];
    __shared__ uint32_t Bs[2][BK][BN + 8];

    const int t = threadIdx.x;
    const int z = blockIdx.z;
    const int b = (MODE == 0) ? (z & 7) : z;
    const int s = (MODE == 0) ? (z >> 3) : 0;
    const int m0 = (MODE == 0) ? blockIdx.y * BM : 0;
    const int n0 = blockIdx.x * BN;

    const float* Xb = ((MODE == 0 && s == 1) ? X1 : X0) + (size_t)b * KDIM * HWP + n0;

    const int warp = t >> 5, lane = t & 31;
    const int gid = lane >> 2, tig = lane & 3;
    const int wm = warp >> 1;
    const int wn = warp & 1;

    float acc[2][8][4];
    #pragma unroll
    for (int mi = 0; mi < 2; mi++)
        #pragma unroll
        for (int ni = 0; ni < 8; ni++)
            #pragma unroll
            for (int r = 0; r < 4; r++) acc[mi][ni][r] = 0.f;

    float4 pa[2], pb[2];

    auto load_global = [&](int kt) {
        const int k0 = kt * BK;
        #pragma unroll
        for (int i = 0; i < 2; i++) {
            int fa = t + i * 256;
            int row = fa >> 2, c4 = fa & 3;
            const float* src;
            if (MODE == 1) {
                src = (row < 64) ? (W0 + (size_t)row * KDIM)
                                 : (W1 + (size_t)(row - 64) * KDIM);
            } else {
                src = W0 + (size_t)(m0 + row) * KDIM;
            }
            pa[i] = *reinterpret_cast<const float4*>(src + k0 + c4 * 4);
            int fb = t + i * 256;
            int krow = fb >> 5, c4b = fb & 31;
            pb[i] = *reinterpret_cast<const float4*>(Xb + (size_t)(k0 + krow) * HWP + c4b * 4);
        }
    };
    auto store_smem = [&](int buf) {
        #pragma unroll
        for (int i = 0; i < 2; i++) {
            int fa = t + i * 256;
            int row = fa >> 2, c4 = fa & 3;
            As[buf][c4 * 4 + 0][row] = f2tf32(pa[i].x);
            As[buf][c4 * 4 + 1][row] = f2tf32(pa[i].y);
            As[buf][c4 * 4 + 2][row] = f2tf32(pa[i].z);
            As[buf][c4 * 4 + 3][row] = f2tf32(pa[i].w);
            int fb = t + i * 256;
            int krow = fb >> 5, c4b = fb & 31;
            uint4 u = {f2tf32(pb[i].x), f2tf32(pb[i].y), f2tf32(pb[i].z), f2tf32(pb[i].w)};
            *reinterpret_cast<uint4*>(&Bs[buf][krow][c4b * 4]) = u;
        }
    };

    load_global(0);
    store_smem(0);
    __syncthreads();

    for (int kt = 0; kt < NKT; kt++) {
        const int cur = kt & 1;
        if (kt + 1 < NKT) load_global(kt + 1);

        #pragma unroll
        for (int ks = 0; ks < 2; ks++) {
            const int kb = ks * 8;
            uint32_t af[2][4];
            #pragma unroll
            for (int mi = 0; mi < 2; mi++) {
                int m = wm * 32 + mi * 16;
                af[mi][0] = As[cur][kb + tig    ][m + gid];
                af[mi][1] = As[cur][kb + tig    ][m + gid + 8];
                af[mi][2] = As[cur][kb + tig + 4][m + gid];
                af[mi][3] = As[cur][kb + tig + 4][m + gid + 8];
            }
            #pragma unroll
            for (int ni = 0; ni < 8; ni++) {
                int n = wn * 64 + ni * 8 + gid;
                uint32_t b0 = Bs[cur][kb + tig    ][n];
                uint32_t b1 = Bs[cur][kb + tig + 4][n];
                #pragma unroll
                for (int mi = 0; mi < 2; mi++) {
                    mma_tf32(acc[mi][ni][0], acc[mi][ni][1], acc[mi][ni][2], acc[mi][ni][3],
                             af[mi][0], af[mi][1], af[mi][2], af[mi][3], b0, b1);
                }
            }
        }

        if (kt + 1 < NKT) store_smem((kt + 1) & 1);
        __syncthreads();
    }

    #pragma unroll
    for (int mi = 0; mi < 2; mi++) {
        int ml = wm * 32 + mi * 16 + gid;
        #pragma unroll
        for (int half = 0; half < 2; half++) {
            int m = m0 + ml + half * 8;
            float bv;
            float* obase;
            if (MODE == 1) {
                if (m < 64) { bv = bias0[m];      obase = O0 + ((size_t)b * 64 + m)       * HWP; }
                else        { bv = bias1[m - 64]; obase = O1 + ((size_t)b * 64 + (m - 64)) * HWP; }
            } else {
                bv = bias0[m];
                float* O = (s == 1) ? O1 : O0;
                obase = O + ((size_t)b * NC + m) * HWP;
            }
            #pragma unroll
            for (int ni = 0; ni < 8; ni++) {
                int n = n0 + wn * 64 + ni * 8 + tig * 2;
                float2 o;
                o.x = acc[mi][ni][half * 2 + 0] + bv;
                o.y = acc[mi][ni][half * 2 + 1] + bv;
                *reinterpret_cast<float2*>(obase + n) = o;
            }
        }
    }
}

// ---------------------------------------------------------------------------
// energy_H (unchanged)
// ---------------------------------------------------------------------------
__global__ void energy_H_kernel(const float* __restrict__ q,
                                const float* __restrict__ k,
                                float* __restrict__ att)
{
    const int w = blockIdx.x, b = blockIdx.y;
    __shared__ float Qs[64][65];
    __shared__ float Ks[64][65];
    const int t = threadIdx.x;
    #pragma unroll
    for (int i = 0; i < 16; i++) {
        int idx = t + i * 256;
        int c = idx >> 6, h = idx & 63;
        size_t g = ((size_t)(b * NCQ + c) * NH + h) * NW + w;
        Qs[c][h] = q[g];
        Ks[c][h] = k[g];
    }
    __syncthreads();
    const int tx = t & 15, ty = t >> 4;
    float acc[4][4];
    #pragma unroll
    for (int i = 0; i < 4; i++)
        #pragma unroll
        for (int j = 0; j < 4; j++) acc[i][j] = 0.f;
    for (int c = 0; c < 64; c++) {
        float qa[4], kb[4];
        #pragma unroll
        for (int i = 0; i < 4; i++) qa[i] = Qs[c][ty * 4 + i];
        #pragma unroll
        for (int j = 0; j < 4; j++) kb[j] = Ks[c][tx * 4 + j];
        #pragma unroll
        for (int i = 0; i < 4; i++)
            #pragma unroll
            for (int j = 0; j < 4; j++) acc[i][j] += qa[i] * kb[j];
    }
    #pragma unroll
    for (int i = 0; i < 4; i++) {
        int h = ty * 4 + i;
        float4 o = {acc[i][0], acc[i][1], acc[i][2], acc[i][3]};
        *reinterpret_cast<float4*>(&att[((size_t)(b * NH + h) * NW + w) * 128 + tx * 4]) = o;
    }
}

// ---------------------------------------------------------------------------
// energy_W (unchanged)
// ---------------------------------------------------------------------------
__global__ void energy_W_kernel(const float* __restrict__ q,
                                const float* __restrict__ k,
                                float* __restrict__ att)
{
    const int h = blockIdx.x, b = blockIdx.y;
    __shared__ float Qs[64][65];
    __shared__ float Ks[64][65];
    const int t = threadIdx.x;
    #pragma unroll
    for (int i = 0; i < 16; i++) {
        int idx = t + i * 256;
        int c = idx >> 6, w = idx & 63;
        size_t g = ((size_t)(b * NCQ + c) * NH + h) * NW + w;
        Qs[c][w] = q[g];
        Ks[c][w] = k[g];
    }
    __syncthreads();
    const int tx = t & 15, ty = t >> 4;
    float acc[4][4];
    #pragma unroll
    for (int i = 0; i < 4; i++)
        #pragma unroll
        for (int j = 0; j < 4; j++) acc[i][j] = 0.f;
    for (int c = 0; c < 64; c++) {
        float qa[4], kb[4];
        #pragma unroll
        for (int i = 0; i < 4; i++) qa[i] = Qs[c][ty * 4 + i];
        #pragma unroll
        for (int j = 0; j < 4; j++) kb[j] = Ks[c][tx * 4 + j];
        #pragma unroll
        for (int i = 0; i < 4; i++)
            #pragma unroll
            for (int j = 0; j < 4; j++) acc[i][j] += qa[i] * kb[j];
    }
    #pragma unroll
    for (int i = 0; i < 4; i++) {
        int w = ty * 4 + i;
        float4 o = {acc[i][0], acc[i][1], acc[i][2], acc[i][3]};
        *reinterpret_cast<float4*>(&att[((size_t)(b * NH + h) * NW + w) * 128 + 64 + tx * 4]) = o;
    }
}

// ---------------------------------------------------------------------------
// softmax (unchanged)
// ---------------------------------------------------------------------------
__global__ void softmax_kernel(float* __restrict__ att)
{
    int gwarp = (blockIdx.x * blockDim.x + threadIdx.x) >> 5;
    int lane  = threadIdx.x & 31;
    if (gwarp >= NB * HWP) return;
    float4* row = reinterpret_cast<float4*>(att) + (size_t)gwarp * 32;
    float4 v = row[lane];
    float m = fmaxf(fmaxf(v.x, v.y), fmaxf(v.z, v.w));
    #pragma unroll
    for (int o = 16; o > 0; o >>= 1) m = fmaxf(m, __shfl_xor_sync(0xFFFFFFFFu, m, o));
    v.x = __expf(v.x - m); v.y = __expf(v.y - m);
    v.z = __expf(v.z - m); v.w = __expf(v.w - m);
    float s = v.x + v.y + v.z + v.w;
    #pragma unroll
    for (int o = 16; o > 0; o >>= 1) s += __shfl_xor_sync(0xFFFFFFFFu, s, o);
    float r = 1.0f / s;
    v.x *= r; v.y *= r; v.z *= r; v.w *= r;
    row[lane] = v;
}

// ---------------------------------------------------------------------------
// aggH_mma: H-direction aggregation + residual, tensor cores.
//   For each of 8 w in the block's w-group, computes
//     Out_w[h][c] = attH_w[h][H'] x V_w[H'][c]      (m64 x n32 x k64 GEMM)
//   accumulators hold all 8 w per (h,c) -> 32B-coalesced y stores:
//     y[b,c,h,w0..7] = x[b,c,h,w0..7] + g*Out
// Block: (wg, s*16+cc, b). 256 threads = 8 warps (4 h-tiles x 2 c16-halves).
// Dynamic smem: Vs[32*517] (c-major, addr c*517+H'*8+w; conflict-free B-frags)
//               As[64*66]  (att rows [h][H'])
// ---------------------------------------------------------------------------
#define VS_PITCH 517
__global__ void __launch_bounds__(256)
aggH_mma(const float* __restrict__ v2, const float* __restrict__ v1,
         const float* __restrict__ x2, const float* __restrict__ x1,
         const float* __restrict__ att, const float* __restrict__ gamma,
         float* __restrict__ y)
{
    extern __shared__ uint32_t sm[];
    uint32_t* Vs = sm;                 // 32*517
    uint32_t* As = sm + 32 * VS_PITCH; // 64*66

    const int t  = threadIdx.x;
    const int wg = blockIdx.x;            // w-group
    const int cs = blockIdx.y;            // s*16 + cc
    const int b  = blockIdx.z;
    const int s  = cs >> 4;
    const int cBase = (cs & 15) * 32;
    const int w0 = wg * 8;

    const float* v = (s == 1) ? v1 : v2;
    const float* x = (s == 1) ? x1 : x2;
    float* yd = y + (size_t)s * NB * NC * HWP;
    const float g = gamma[0];

    // Load V tile: 32 c-rows x 64 H' x 8 w (coalesced 32B per (c,H'))
    #pragma unroll
    for (int i = 0; i < 8; i++) {
        int rr = t + i * 256;            // 0..2047
        int ci = rr >> 6, hp = rr & 63;
        const float* src = v + ((size_t)(b * NC + cBase + ci) * NH + hp) * NW + w0;
        float4 u0 = *reinterpret_cast<const float4*>(src);
        float4 u1 = *reinterpret_cast<const float4*>(src + 4);
        uint32_t* d = Vs + ci * VS_PITCH + hp * 8;
        d[0] = f2tf32(u0.x); d[1] = f2tf32(u0.y); d[2] = f2tf32(u0.z); d[3] = f2tf32(u0.w);
        d[4] = f2tf32(u1.x); d[5] = f2tf32(u1.y); d[6] = f2tf32(u1.z); d[7] = f2tf32(u1.w);
    }

    const int warp = t >> 5, lane = t & 31;
    const int gid = lane >> 2, tig = lane & 3;
    const int mi = warp >> 1;          // h-tile (m16)
    const int nh = warp & 1;           // c16 half

    float acc[8][2][4];
    #pragma unroll
    for (int w = 0; w < 8; w++)
        #pragma unroll
        for (int ni = 0; ni < 2; ni++)
            #pragma unroll
            for (int r = 0; r < 4; r++) acc[w][ni][r] = 0.f;

    for (int w = 0; w < 8; w++) {
        __syncthreads();
        // load att H-part rows for this w: As[h][H']
        #pragma unroll
        for (int i = 0; i < 4; i++) {
            int f = t + i * 256;          // 0..1023
            int h = f >> 4, q = f & 15;
            const float* src = att + ((size_t)(b * NH + h) * NW + (w0 + w)) * 128 + q * 4;
            float4 u = *reinterpret_cast<const float4*>(src);
            uint32_t* d = As + h * 66 + q * 4;
            d[0] = f2tf32(u.x); d[1] = f2tf32(u.y); d[2] = f2tf32(u.z); d[3] = f2tf32(u.w);
        }
        __syncthreads();

        #pragma unroll
        for (int k = 0; k < 8; k++) {
            const int k0 = k * 8;
            const int m = mi * 16;
            uint32_t a0 = As[(m + gid    ) * 66 + k0 + tig    ];
            uint32_t a1 = As[(m + gid + 8) * 66 + k0 + tig    ];
            uint32_t a2 = As[(m + gid    ) * 66 + k0 + tig + 4];
            uint32_t a3 = As[(m + gid + 8) * 66 + k0 + tig + 4];
            #pragma unroll
            for (int ni = 0; ni < 2; ni++) {
                int n = nh * 16 + ni * 8 + gid;   // local c
                uint32_t b0 = Vs[n * VS_PITCH + (k0 + tig    ) * 8 + w];
                uint32_t b1 = Vs[n * VS_PITCH + (k0 + tig + 4) * 8 + w];
                mma_tf32(acc[w][ni][0], acc[w][ni][1], acc[w][ni][2], acc[w][ni][3],
                         a0, a1, a2, a3, b0, b1);
            }
        }
    }

    // Epilogue: per (h,c) slot gather 8 w values -> y = x + g*out (32B stores)
    #pragma unroll
    for (int ni = 0; ni < 2; ni++) {
        #pragma unroll
        for (int rh = 0; rh < 2; rh++) {
            #pragma unroll
            for (int cp = 0; cp < 2; cp++) {
                int h = mi * 16 + gid + rh * 8;
                int c = cBase + nh * 16 + ni * 8 + tig * 2 + cp;
                size_t base = ((size_t)(b * NC + c) * NH + h) * NW + w0;
                float4 xa = *reinterpret_cast<const float4*>(x + base);
                float4 xb = *reinterpret_cast<const float4*>(x + base + 4);
                float4 oa, ob;
                oa.x = xa.x + g * acc[0][ni][rh * 2 + cp];
                oa.y = xa.y + g * acc[1][ni][rh * 2 + cp];
                oa.z = xa.z + g * acc[2][ni][rh * 2 + cp];
                oa.w = xa.w + g * acc[3][ni][rh * 2 + cp];
                ob.x = xb.x + g * acc[4][ni][rh * 2 + cp];
                ob.y = xb.y + g * acc[5][ni][rh * 2 + cp];
                ob.z = xb.z + g * acc[6][ni][rh * 2 + cp];
                ob.w = xb.w + g * acc[7][ni][rh * 2 + cp];
                *reinterpret_cast<float4*>(yd + base)     = oa;
                *reinterpret_cast<float4*>(yd + base + 4) = ob;
            }
        }
    }
}

// ---------------------------------------------------------------------------
// aggW_mma: W-direction aggregation, accumulate into y (RMW), tensor cores.
//   Out[w][c] = attW_h[w][W'] x V_h[W'][c]   (m64 x n64 x k64 per (b,h,cchunk,s))
//   y[b,c,h,w] += g*Out[w][c]
// Block: (h, s*8+cc, b). 256 threads = 8 warps (4 w-tiles x 2 c32-halves).
// ---------------------------------------------------------------------------
__global__ void __launch_bounds__(256)
aggW_mma(const float* __restrict__ v2, const float* __restrict__ v1,
         const float* __restrict__ att, const float* __restrict__ gamma,
         float* __restrict__ y)
{
    __shared__ uint32_t As[64 * 66];   // att W-part rows [w][W']
    __shared__ uint32_t Vs[64 * 66];   // v rows [c][W']

    const int t  = threadIdx.x;
    const int h  = blockIdx.x;
    const int cs = blockIdx.y;           // s*8 + cc
    const int b  = blockIdx.z;
    const int s  = cs >> 3;
    const int cBase = (cs & 7) * 64;

    const float* v = (s == 1) ? v1 : v2;
    float* yd = y + (size_t)s * NB * NC * HWP;
    const float g = gamma[0];

    #pragma unroll
    for (int i = 0; i < 4; i++) {
        int f = t + i * 256;
        int r = f >> 4, q = f & 15;
        // att W-half
        const float* sa = att + ((size_t)(b * NH + h) * NW + r) * 128 + 64 + q * 4;
        float4 ua = *reinterpret_cast<const float4*>(sa);
        uint32_t* da = As + r * 66 + q * 4;
        da[0] = f2tf32(ua.x); da[1] = f2tf32(ua.y); da[2] = f2tf32(ua.z); da[3] = f2tf32(ua.w);
        // v rows (c = r)
        const float* sv = v + ((size_t)(b * NC + cBase + r) * NH + h) * NW + q * 4;
        float4 uv = *reinterpret_cast<const float4*>(sv);
        uint32_t* dv = Vs + r * 66 + q * 4;
        dv[0] = f2tf32(uv.x); dv[1] = f2tf32(uv.y); dv[2] = f2tf32(uv.z); dv[3] = f2tf32(uv.w);
    }
    __syncthreads();

    const int warp = t >> 5, lane = t & 31;
    const int gid = lane >> 2, tig = lane & 3;
    const int mi = warp >> 1;          // w-tile
    const int nh = warp & 1;           // c32 half

    float acc[4][4];
    #pragma unroll
    for (int ni = 0; ni < 4; ni++)
        #pragma unroll
        for (int r = 0; r < 4; r++) acc[ni][r] = 0.f;

    #pragma unroll
    for (int k = 0; k < 8; k++) {
        const int k0 = k * 8;
        const int m = mi * 16;
        uint32_t a0 = As[(m + gid    ) * 66 + k0 + tig    ];
        uint32_t a1 = As[(m + gid + 8) * 66 + k0 + tig    ];
        uint32_t a2 = As[(m + gid    ) * 66 + k0 + tig + 4];
        uint32_t a3 = As[(m + gid + 8) * 66 + k0 + tig + 4];
        #pragma unroll
        for (int ni = 0; ni < 4; ni++) {
            int n = nh * 32 + ni * 8 + gid;   // local c
            uint32_t b0 = Vs[n * 66 + k0 + tig    ];
            uint32_t b1 = Vs[n * 66 + k0 + tig + 4];
            mma_tf32(acc[ni][0], acc[ni][1], acc[ni][2], acc[ni][3],
                     a0, a1, a2, a3, b0, b1);
        }
    }

    // RMW epilogue: y[b,c,h,w] += g*acc  (8-lane 32B clusters per store)
    #pragma unroll
    for (int ni = 0; ni < 4; ni++) {
        #pragma unroll
        for (int rh = 0; rh < 2; rh++) {
            int w = mi * 16 + gid + rh * 8;
            #pragma unroll
            for (int cp = 0; cp < 2; cp++) {
                int c = cBase + nh * 32 + ni * 8 + tig * 2 + cp;
                size_t idx = ((size_t)(b * NC + c) * NH + h) * NW + w;
                yd[idx] += g * acc[ni][rh * 2 + cp];
            }
        }
    }
}

// ---------------------------------------------------------------------------
extern "C" void kernel_launch(void* const* d_in, const int* in_sizes, int n_in,
                              void* d_out, int out_size)
{
    const float* x2    = (const float*)d_in[0];
    const float* x1    = (const float*)d_in[1];
    const float* q_w   = (const float*)d_in[2];
    const float* q_b   = (const float*)d_in[3];
    const float* k_w   = (const float*)d_in[4];
    const float* k_b   = (const float*)d_in[5];
    const float* v_w   = (const float*)d_in[6];
    const float* v_b   = (const float*)d_in[7];
    const float* gamma = (const float*)d_in[8];
    float* y = (float*)d_out;

    float *gq, *gk, *gv2, *gv1, *gatt;
    cudaGetSymbolAddress((void**)&gq,  g_q);
    cudaGetSymbolAddress((void**)&gk,  g_k);
    cudaGetSymbolAddress((void**)&gv2, g_v2);
    cudaGetSymbolAddress((void**)&gv1, g_v1);
    cudaGetSymbolAddress((void**)&gatt, g_att);

    const int aggH_smem = (32 * VS_PITCH + 64 * 66) * 4;   // ~83 KB
    cudaFuncSetAttribute(aggH_mma, cudaFuncAttributeMaxDynamicSharedMemorySize, aggH_smem);

    // Projections (tf32 tensor cores)
    gemm_tf32<0><<<dim3(32, 4, 16), 256>>>(v_w, v_b, nullptr, nullptr, x2, x1, gv2, gv1);
    gemm_tf32<1><<<dim3(32, 1, 8),  256>>>(q_w, q_b, k_w, k_b, x2, nullptr, gq, gk);

    // Energies + softmax
    energy_H_kernel<<<dim3(NW, NB), 256>>>(gq, gk, gatt);
    energy_W_kernel<<<dim3(NH, NB), 256>>>(gq, gk, gatt);
    softmax_kernel<<<(NB * HWP) / 8, 256>>>(gatt);

    // Aggregation + residual (tensor cores)
    aggH_mma<<<dim3(8, 32, NB), 256, aggH_smem>>>(gv2, gv1, x2, x1, gatt, gamma, y);
    aggW_mma<<<dim3(NH, 16, NB), 256>>>(gv2, gv1, gatt, gamma, y);
}

// round 4
// speedup vs baseline: 2.5950x; 1.0000x over previous
#include <cuda_runtime.h>
#include <cstddef>
#include <cstdint>

// Problem constants
#define NB 8
#define NC 512
#define NH 64
#define NW 64
#define NCQ 64
#define HWP 4096   // NH*NW
#define KDIM 512

// Scratch (statically allocated device globals; no cudaMalloc allowed)
__device__ float g_q  [NB * NCQ * HWP];   // 8 MB
__device__ float g_k  [NB * NCQ * HWP];   // 8 MB
__device__ float g_v2 [NB * NC  * HWP];   // 64 MB
__device__ float g_v1 [NB * NC  * HWP];   // 64 MB
__device__ float g_att[NB * HWP * 128];   // 16 MB  [b,h,w, 0:64]=E_H, [64:128]=E_W

__device__ __forceinline__ uint32_t f2tf32(float f) {
    uint32_t u;
    asm("cvt.rna.tf32.f32 %0, %1;" : "=r"(u) : "f"(f));
    return u;
}

__device__ __forceinline__ void mma_tf32(float& d0, float& d1, float& d2, float& d3,
                                         uint32_t a0, uint32_t a1, uint32_t a2, uint32_t a3,
                                         uint32_t b0, uint32_t b1) {
    asm volatile(
        "mma.sync.aligned.m16n8k8.row.col.f32.tf32.tf32.f32 "
        "{%0,%1,%2,%3}, {%4,%5,%6,%7}, {%8,%9}, {%0,%1,%2,%3};"
        : "+f"(d0), "+f"(d1), "+f"(d2), "+f"(d3)
        : "r"(a0), "r"(a1), "r"(a2), "r"(a3), "r"(b0), "r"(b1));
}

__device__ __forceinline__ void cp_async16(void* smem_dst, const void* gsrc) {
    uint32_t d = (uint32_t)__cvta_generic_to_shared(smem_dst);
    asm volatile("cp.async.cg.shared.global [%0], [%1], 16;\n" :: "r"(d), "l"(gsrc));
}
#define CP_COMMIT() asm volatile("cp.async.commit_group;\n" ::: "memory")
#define CP_WAIT0()  asm volatile("cp.async.wait_group 0;\n" ::: "memory")

// ---------------------------------------------------------------------------
// tf32 tensor-core GEMM for the 1x1-conv projections.
// B (X tile) staged raw via cp.async (cvt at fragment read); A converted on
// the register->smem store path. Double buffered.
// ---------------------------------------------------------------------------
template<int MODE>
__global__ void __launch_bounds__(256)
gemm_tf32(const float* __restrict__ W0, const float* __restrict__ bias0,
          const float* __restrict__ W1, const float* __restrict__ bias1,
          const float* __restrict__ X0, const float* __restrict__ X1,
          float* __restrict__ O0, float* __restrict__ O1)
{
    constexpr int BM = 128, BN = 128, BK = 16;
    constexpr int NKT = KDIM / BK;

    __shared__ uint32_t As[2][BK][BM + 4];   // tf32 [k][m]
    __shared__ float    Bs[2][BK][BN + 8];   // raw float [k][n]

    const int t = threadIdx.x;
    const int z = blockIdx.z;
    const int b = (MODE == 0) ? (z & 7) : z;
    const int s = (MODE == 0) ? (z >> 3) : 0;
    const int m0 = (MODE == 0) ? blockIdx.y * BM : 0;
    const int n0 = blockIdx.x * BN;

    const float* Xb = ((MODE == 0 && s == 1) ? X1 : X0) + (size_t)b * KDIM * HWP + n0;

    const int warp = t >> 5, lane = t & 31;
    const int gid = lane >> 2, tig = lane & 3;
    const int wm = warp >> 1;
    const int wn = warp & 1;

    float acc[2][8][4];
    #pragma unroll
    for (int mi = 0; mi < 2; mi++)
        #pragma unroll
        for (int ni = 0; ni < 8; ni++)
            #pragma unroll
            for (int r = 0; r < 4; r++) acc[mi][ni][r] = 0.f;

    float4 pa[2];

    auto issue_B = [&](int kt, int buf) {
        const int k0 = kt * BK;
        #pragma unroll
        for (int i = 0; i < 2; i++) {
            int fb = t + i * 256;
            int krow = fb >> 5, c4b = fb & 31;
            cp_async16(&Bs[buf][krow][c4b * 4],
                       Xb + (size_t)(k0 + krow) * HWP + c4b * 4);
        }
    };
    auto load_A = [&](int kt) {
        const int k0 = kt * BK;
        #pragma unroll
        for (int i = 0; i < 2; i++) {
            int fa = t + i * 256;
            int row = fa >> 2, c4 = fa & 3;
            const float* src;
            if (MODE == 1) {
                src = (row < 64) ? (W0 + (size_t)row * KDIM)
                                 : (W1 + (size_t)(row - 64) * KDIM);
            } else {
                src = W0 + (size_t)(m0 + row) * KDIM;
            }
            pa[i] = *reinterpret_cast<const float4*>(src + k0 + c4 * 4);
        }
    };
    auto store_A = [&](int buf) {
        #pragma unroll
        for (int i = 0; i < 2; i++) {
            int fa = t + i * 256;
            int row = fa >> 2, c4 = fa & 3;
            As[buf][c4 * 4 + 0][row] = f2tf32(pa[i].x);
            As[buf][c4 * 4 + 1][row] = f2tf32(pa[i].y);
            As[buf][c4 * 4 + 2][row] = f2tf32(pa[i].z);
            As[buf][c4 * 4 + 3][row] = f2tf32(pa[i].w);
        }
    };

    issue_B(0, 0); CP_COMMIT();
    load_A(0);
    store_A(0);
    CP_WAIT0();
    __syncthreads();

    for (int kt = 0; kt < NKT; kt++) {
        const int cur = kt & 1;
        if (kt + 1 < NKT) {
            issue_B(kt + 1, cur ^ 1); CP_COMMIT();
            load_A(kt + 1);
        }

        #pragma unroll
        for (int ks = 0; ks < 2; ks++) {
            const int kb = ks * 8;
            uint32_t af[2][4];
            #pragma unroll
            for (int mi = 0; mi < 2; mi++) {
                int m = wm * 32 + mi * 16;
                af[mi][0] = As[cur][kb + tig    ][m + gid];
                af[mi][1] = As[cur][kb + tig    ][m + gid + 8];
                af[mi][2] = As[cur][kb + tig + 4][m + gid];
                af[mi][3] = As[cur][kb + tig + 4][m + gid + 8];
            }
            #pragma unroll
            for (int ni = 0; ni < 8; ni++) {
                int n = wn * 64 + ni * 8 + gid;
                uint32_t b0 = f2tf32(Bs[cur][kb + tig    ][n]);
                uint32_t b1 = f2tf32(Bs[cur][kb + tig + 4][n]);
                #pragma unroll
                for (int mi = 0; mi < 2; mi++) {
                    mma_tf32(acc[mi][ni][0], acc[mi][ni][1], acc[mi][ni][2], acc[mi][ni][3],
                             af[mi][0], af[mi][1], af[mi][2], af[mi][3], b0, b1);
                }
            }
        }

        if (kt + 1 < NKT) {
            store_A(cur ^ 1);
            CP_WAIT0();
            __syncthreads();
        }
    }

    #pragma unroll
    for (int mi = 0; mi < 2; mi++) {
        int ml = wm * 32 + mi * 16 + gid;
        #pragma unroll
        for (int half = 0; half < 2; half++) {
            int m = m0 + ml + half * 8;
            float bv;
            float* obase;
            if (MODE == 1) {
                if (m < 64) { bv = bias0[m];      obase = O0 + ((size_t)b * 64 + m)       * HWP; }
                else        { bv = bias1[m - 64]; obase = O1 + ((size_t)b * 64 + (m - 64)) * HWP; }
            } else {
                bv = bias0[m];
                float* O = (s == 1) ? O1 : O0;
                obase = O + ((size_t)b * NC + m) * HWP;
            }
            #pragma unroll
            for (int ni = 0; ni < 8; ni++) {
                int n = n0 + wn * 64 + ni * 8 + tig * 2;
                float2 o;
                o.x = acc[mi][ni][half * 2 + 0] + bv;
                o.y = acc[mi][ni][half * 2 + 1] + bv;
                *reinterpret_cast<float2*>(obase + n) = o;
            }
        }
    }
}

// ---------------------------------------------------------------------------
// energy_H (unchanged)
// ---------------------------------------------------------------------------
__global__ void energy_H_kernel(const float* __restrict__ q,
                                const float* __restrict__ k,
                                float* __restrict__ att)
{
    const int w = blockIdx.x, b = blockIdx.y;
    __shared__ float Qs[64][65];
    __shared__ float Ks[64][65];
    const int t = threadIdx.x;
    #pragma unroll
    for (int i = 0; i < 16; i++) {
        int idx = t + i * 256;
        int c = idx >> 6, h = idx & 63;
        size_t g = ((size_t)(b * NCQ + c) * NH + h) * NW + w;
        Qs[c][h] = q[g];
        Ks[c][h] = k[g];
    }
    __syncthreads();
    const int tx = t & 15, ty = t >> 4;
    float acc[4][4];
    #pragma unroll
    for (int i = 0; i < 4; i++)
        #pragma unroll
        for (int j = 0; j < 4; j++) acc[i][j] = 0.f;
    for (int c = 0; c < 64; c++) {
        float qa[4], kb[4];
        #pragma unroll
        for (int i = 0; i < 4; i++) qa[i] = Qs[c][ty * 4 + i];
        #pragma unroll
        for (int j = 0; j < 4; j++) kb[j] = Ks[c][tx * 4 + j];
        #pragma unroll
        for (int i = 0; i < 4; i++)
            #pragma unroll
            for (int j = 0; j < 4; j++) acc[i][j] += qa[i] * kb[j];
    }
    #pragma unroll
    for (int i = 0; i < 4; i++) {
        int h = ty * 4 + i;
        float4 o = {acc[i][0], acc[i][1], acc[i][2], acc[i][3]};
        *reinterpret_cast<float4*>(&att[((size_t)(b * NH + h) * NW + w) * 128 + tx * 4]) = o;
    }
}

// ---------------------------------------------------------------------------
// energy_W (unchanged)
// ---------------------------------------------------------------------------
__global__ void energy_W_kernel(const float* __restrict__ q,
                                const float* __restrict__ k,
                                float* __restrict__ att)
{
    const int h = blockIdx.x, b = blockIdx.y;
    __shared__ float Qs[64][65];
    __shared__ float Ks[64][65];
    const int t = threadIdx.x;
    #pragma unroll
    for (int i = 0; i < 16; i++) {
        int idx = t + i * 256;
        int c = idx >> 6, w = idx & 63;
        size_t g = ((size_t)(b * NCQ + c) * NH + h) * NW + w;
        Qs[c][w] = q[g];
        Ks[c][w] = k[g];
    }
    __syncthreads();
    const int tx = t & 15, ty = t >> 4;
    float acc[4][4];
    #pragma unroll
    for (int i = 0; i < 4; i++)
        #pragma unroll
        for (int j = 0; j < 4; j++) acc[i][j] = 0.f;
    for (int c = 0; c < 64; c++) {
        float qa[4], kb[4];
        #pragma unroll
        for (int i = 0; i < 4; i++) qa[i] = Qs[c][ty * 4 + i];
        #pragma unroll
        for (int j = 0; j < 4; j++) kb[j] = Ks[c][tx * 4 + j];
        #pragma unroll
        for (int i = 0; i < 4; i++)
            #pragma unroll
            for (int j = 0; j < 4; j++) acc[i][j] += qa[i] * kb[j];
    }
    #pragma unroll
    for (int i = 0; i < 4; i++) {
        int w = ty * 4 + i;
        float4 o = {acc[i][0], acc[i][1], acc[i][2], acc[i][3]};
        *reinterpret_cast<float4*>(&att[((size_t)(b * NH + h) * NW + w) * 128 + 64 + tx * 4]) = o;
    }
}

// ---------------------------------------------------------------------------
// softmax (unchanged)
// ---------------------------------------------------------------------------
__global__ void softmax_kernel(float* __restrict__ att)
{
    int gwarp = (blockIdx.x * blockDim.x + threadIdx.x) >> 5;
    int lane  = threadIdx.x & 31;
    if (gwarp >= NB * HWP) return;
    float4* row = reinterpret_cast<float4*>(att) + (size_t)gwarp * 32;
    float4 v = row[lane];
    float m = fmaxf(fmaxf(v.x, v.y), fmaxf(v.z, v.w));
    #pragma unroll
    for (int o = 16; o > 0; o >>= 1) m = fmaxf(m, __shfl_xor_sync(0xFFFFFFFFu, m, o));
    v.x = __expf(v.x - m); v.y = __expf(v.y - m);
    v.z = __expf(v.z - m); v.w = __expf(v.w - m);
    float s = v.x + v.y + v.z + v.w;
    #pragma unroll
    for (int o = 16; o > 0; o >>= 1) s += __shfl_xor_sync(0xFFFFFFFFu, s, o);
    float r = 1.0f / s;
    v.x *= r; v.y *= r; v.z *= r; v.w *= r;
    row[lane] = v;
}

// ---------------------------------------------------------------------------
// aggH_mma: H-direction aggregation + residual, tensor cores.
// att tiles double-buffered via cp.async (raw float, cvt at fragment read).
// ---------------------------------------------------------------------------
#define VS_PITCH 517
#define AS_PITCH 68
__global__ void __launch_bounds__(256)
aggH_mma(const float* __restrict__ v2, const float* __restrict__ v1,
         const float* __restrict__ x2, const float* __restrict__ x1,
         const float* __restrict__ att, const float* __restrict__ gamma,
         float* __restrict__ y)
{
    extern __shared__ uint32_t sm[];
    uint32_t* Vs = sm;                                  // 32*517 (tf32)
    float*    AsF = reinterpret_cast<float*>(sm + 32 * VS_PITCH); // 2*64*68 raw

    const int t  = threadIdx.x;
    const int wg = blockIdx.x;            // w-group
    const int cs = blockIdx.y;            // s*16 + cc
    const int b  = blockIdx.z;
    const int s  = cs >> 4;
    const int cBase = (cs & 15) * 32;
    const int w0 = wg * 8;

    const float* v = (s == 1) ? v1 : v2;
    const float* x = (s == 1) ? x1 : x2;
    float* yd = y + (size_t)s * NB * NC * HWP;
    const float g = gamma[0];

    auto issue_att = [&](int w, int buf) {
        // 64 rows of 64 floats; 4 x 16B chunks per thread
        #pragma unroll
        for (int i = 0; i < 4; i++) {
            int f = t + i * 256;
            int h = f >> 4, q = f & 15;
            cp_async16(AsF + (size_t)buf * 64 * AS_PITCH + h * AS_PITCH + q * 4,
                       att + ((size_t)(b * NH + h) * NW + (w0 + w)) * 128 + q * 4);
        }
    };

    issue_att(0, 0); CP_COMMIT();

    // Load V tile: 32 c-rows x 64 H' x 8 w (coalesced 32B per (c,H'))
    #pragma unroll
    for (int i = 0; i < 8; i++) {
        int rr = t + i * 256;
        int ci = rr >> 6, hp = rr & 63;
        const float* src = v + ((size_t)(b * NC + cBase + ci) * NH + hp) * NW + w0;
        float4 u0 = *reinterpret_cast<const float4*>(src);
        float4 u1 = *reinterpret_cast<const float4*>(src + 4);
        uint32_t* d = Vs + ci * VS_PITCH + hp * 8;
        d[0] = f2tf32(u0.x); d[1] = f2tf32(u0.y); d[2] = f2tf32(u0.z); d[3] = f2tf32(u0.w);
        d[4] = f2tf32(u1.x); d[5] = f2tf32(u1.y); d[6] = f2tf32(u1.z); d[7] = f2tf32(u1.w);
    }
    CP_WAIT0();
    __syncthreads();

    const int warp = t >> 5, lane = t & 31;
    const int gid = lane >> 2, tig = lane & 3;
    const int mi = warp >> 1;          // h-tile (m16)
    const int nh = warp & 1;           // c16 half

    float acc[8][2][4];
    #pragma unroll
    for (int w = 0; w < 8; w++)
        #pragma unroll
        for (int ni = 0; ni < 2; ni++)
            #pragma unroll
            for (int r = 0; r < 4; r++) acc[w][ni][r] = 0.f;

    for (int w = 0; w < 8; w++) {
        const int cur = w & 1;
        if (w + 1 < 8) { issue_att(w + 1, cur ^ 1); CP_COMMIT(); }

        const float* Ac = AsF + (size_t)cur * 64 * AS_PITCH;
        #pragma unroll
        for (int k = 0; k < 8; k++) {
            const int k0 = k * 8;
            const int m = mi * 16;
            uint32_t a0 = f2tf32(Ac[(m + gid    ) * AS_PITCH + k0 + tig    ]);
            uint32_t a1 = f2tf32(Ac[(m + gid + 8) * AS_PITCH + k0 + tig    ]);
            uint32_t a2 = f2tf32(Ac[(m + gid    ) * AS_PITCH + k0 + tig + 4]);
            uint32_t a3 = f2tf32(Ac[(m + gid + 8) * AS_PITCH + k0 + tig + 4]);
            #pragma unroll
            for (int ni = 0; ni < 2; ni++) {
                int n = nh * 16 + ni * 8 + gid;   // local c
                uint32_t b0 = Vs[n * VS_PITCH + (k0 + tig    ) * 8 + w];
                uint32_t b1 = Vs[n * VS_PITCH + (k0 + tig + 4) * 8 + w];
                mma_tf32(acc[w][ni][0], acc[w][ni][1], acc[w][ni][2], acc[w][ni][3],
                         a0, a1, a2, a3, b0, b1);
            }
        }
        if (w + 1 < 8) { CP_WAIT0(); __syncthreads(); }
    }

    // Epilogue: per (h,c) slot gather 8 w values -> y = x + g*out (32B stores)
    #pragma unroll
    for (int ni = 0; ni < 2; ni++) {
        #pragma unroll
        for (int rh = 0; rh < 2; rh++) {
            #pragma unroll
            for (int cp = 0; cp < 2; cp++) {
                int h = mi * 16 + gid + rh * 8;
                int c = cBase + nh * 16 + ni * 8 + tig * 2 + cp;
                size_t base = ((size_t)(b * NC + c) * NH + h) * NW + w0;
                float4 xa = *reinterpret_cast<const float4*>(x + base);
                float4 xb = *reinterpret_cast<const float4*>(x + base + 4);
                float4 oa, ob;
                oa.x = xa.x + g * acc[0][ni][rh * 2 + cp];
                oa.y = xa.y + g * acc[1][ni][rh * 2 + cp];
                oa.z = xa.z + g * acc[2][ni][rh * 2 + cp];
                oa.w = xa.w + g * acc[3][ni][rh * 2 + cp];
                ob.x = xb.x + g * acc[4][ni][rh * 2 + cp];
                ob.y = xb.y + g * acc[5][ni][rh * 2 + cp];
                ob.z = xb.z + g * acc[6][ni][rh * 2 + cp];
                ob.w = xb.w + g * acc[7][ni][rh * 2 + cp];
                *reinterpret_cast<float4*>(yd + base)     = oa;
                *reinterpret_cast<float4*>(yd + base + 4) = ob;
            }
        }
    }
}

// ---------------------------------------------------------------------------
// aggW_mma (unchanged from R3)
// ---------------------------------------------------------------------------
__global__ void __launch_bounds__(256)
aggW_mma(const float* __restrict__ v2, const float* __restrict__ v1,
         const float* __restrict__ att, const float* __restrict__ gamma,
         float* __restrict__ y)
{
    __shared__ uint32_t As[64 * 66];
    __shared__ uint32_t Vs[64 * 66];

    const int t  = threadIdx.x;
    const int h  = blockIdx.x;
    const int cs = blockIdx.y;
    const int b  = blockIdx.z;
    const int s  = cs >> 3;
    const int cBase = (cs & 7) * 64;

    const float* v = (s == 1) ? v1 : v2;
    float* yd = y + (size_t)s * NB * NC * HWP;
    const float g = gamma[0];

    #pragma unroll
    for (int i = 0; i < 4; i++) {
        int f = t + i * 256;
        int r = f >> 4, q = f & 15;
        const float* sa = att + ((size_t)(b * NH + h) * NW + r) * 128 + 64 + q * 4;
        float4 ua = *reinterpret_cast<const float4*>(sa);
        uint32_t* da = As + r * 66 + q * 4;
        da[0] = f2tf32(ua.x); da[1] = f2tf32(ua.y); da[2] = f2tf32(ua.z); da[3] = f2tf32(ua.w);
        const float* sv = v + ((size_t)(b * NC + cBase + r) * NH + h) * NW + q * 4;
        float4 uv = *reinterpret_cast<const float4*>(sv);
        uint32_t* dv = Vs + r * 66 + q * 4;
        dv[0] = f2tf32(uv.x); dv[1] = f2tf32(uv.y); dv[2] = f2tf32(uv.z); dv[3] = f2tf32(uv.w);
    }
    __syncthreads();

    const int warp = t >> 5, lane = t & 31;
    const int gid = lane >> 2, tig = lane & 3;
    const int mi = warp >> 1;
    const int nh = warp & 1;

    float acc[4][4];
    #pragma unroll
    for (int ni = 0; ni < 4; ni++)
        #pragma unroll
        for (int r = 0; r < 4; r++) acc[ni][r] = 0.f;

    #pragma unroll
    for (int k = 0; k < 8; k++) {
        const int k0 = k * 8;
        const int m = mi * 16;
        uint32_t a0 = As[(m + gid    ) * 66 + k0 + tig    ];
        uint32_t a1 = As[(m + gid + 8) * 66 + k0 + tig    ];
        uint32_t a2 = As[(m + gid    ) * 66 + k0 + tig + 4];
        uint32_t a3 = As[(m + gid + 8) * 66 + k0 + tig + 4];
        #pragma unroll
        for (int ni = 0; ni < 4; ni++) {
            int n = nh * 32 + ni * 8 + gid;
            uint32_t b0 = Vs[n * 66 + k0 + tig    ];
            uint32_t b1 = Vs[n * 66 + k0 + tig + 4];
            mma_tf32(acc[ni][0], acc[ni][1], acc[ni][2], acc[ni][3],
                     a0, a1, a2, a3, b0, b1);
        }
    }

    #pragma unroll
    for (int ni = 0; ni < 4; ni++) {
        #pragma unroll
        for (int rh = 0; rh < 2; rh++) {
            int w = mi * 16 + gid + rh * 8;
            #pragma unroll
            for (int cp = 0; cp < 2; cp++) {
                int c = cBase + nh * 32 + ni * 8 + tig * 2 + cp;
                size_t idx = ((size_t)(b * NC + c) * NH + h) * NW + w;
                yd[idx] += g * acc[ni][rh * 2 + cp];
            }
        }
    }
}

// ---------------------------------------------------------------------------
extern "C" void kernel_launch(void* const* d_in, const int* in_sizes, int n_in,
                              void* d_out, int out_size)
{
    const float* x2    = (const float*)d_in[0];
    const float* x1    = (const float*)d_in[1];
    const float* q_w   = (const float*)d_in[2];
    const float* q_b   = (const float*)d_in[3];
    const float* k_w   = (const float*)d_in[4];
    const float* k_b   = (const float*)d_in[5];
    const float* v_w   = (const float*)d_in[6];
    const float* v_b   = (const float*)d_in[7];
    const float* gamma = (const float*)d_in[8];
    float* y = (float*)d_out;

    float *gq, *gk, *gv2, *gv1, *gatt;
    cudaGetSymbolAddress((void**)&gq,  g_q);
    cudaGetSymbolAddress((void**)&gk,  g_k);
    cudaGetSymbolAddress((void**)&gv2, g_v2);
    cudaGetSymbolAddress((void**)&gv1, g_v1);
    cudaGetSymbolAddress((void**)&gatt, g_att);

    static cudaStream_t s2 = nullptr;
    static cudaEvent_t ev1 = nullptr, ev2 = nullptr;
    if (!s2) {
        cudaStreamCreate(&s2);
        cudaEventCreateWithFlags(&ev1, cudaEventDisableTiming);
        cudaEventCreateWithFlags(&ev2, cudaEventDisableTiming);
    }

    const int aggH_smem = (32 * VS_PITCH + 2 * 64 * AS_PITCH) * 4;   // ~101 KB
    cudaFuncSetAttribute(aggH_mma, cudaFuncAttributeMaxDynamicSharedMemorySize, aggH_smem);

    // q/k projection first so the side chain can start early
    gemm_tf32<1><<<dim3(32, 1, 8), 256>>>(q_w, q_b, k_w, k_b, x2, nullptr, gq, gk);
    cudaEventRecord(ev1, 0);

    // side stream: energies + softmax (depends only on q/k)
    cudaStreamWaitEvent(s2, ev1, 0);
    energy_H_kernel<<<dim3(NW, NB), 256, 0, s2>>>(gq, gk, gatt);
    energy_W_kernel<<<dim3(NH, NB), 256, 0, s2>>>(gq, gk, gatt);
    softmax_kernel<<<(NB * HWP) / 8, 256, 0, s2>>>(gatt);
    cudaEventRecord(ev2, s2);

    // main stream: v projections (long) run concurrently with side chain
    gemm_tf32<0><<<dim3(32, 4, 16), 256>>>(v_w, v_b, nullptr, nullptr, x2, x1, gv2, gv1);

    // join, then aggregation
    cudaStreamWaitEvent(0, ev2, 0);
    aggH_mma<<<dim3(8, 32, NB), 256, aggH_smem>>>(gv2, gv1, x2, x1, gatt, gamma, y);
    aggW_mma<<<dim3(NH, 16, NB), 256>>>(gv2, gv1, gatt, gamma, y);
}

// round 6
// speedup vs baseline: 2.9748x; 1.1464x over previous
#include <cuda_runtime.h>
#include <cuda_fp16.h>
#include <cstddef>
#include <cstdint>

// Problem constants
#define NB 8
#define NC 512
#define NH 64
#define NW 64
#define NCQ 64
#define HWP 4096   // NH*NW
#define KDIM 512

// Scratch (statically allocated device globals; no cudaMalloc allowed)
__device__ float g_q  [NB * NCQ * HWP];
__device__ float g_k  [NB * NCQ * HWP];
__device__ float g_v2 [NB * NC  * HWP];
__device__ float g_v1 [NB * NC  * HWP];
__device__ float g_att[NB * HWP * 128];

__device__ __forceinline__ uint32_t pack_h2(float a, float b) {
    __half2 h = __floats2half2_rn(a, b);
    return *reinterpret_cast<uint32_t*>(&h);
}

__device__ __forceinline__ void mma_tf32(float& d0, float& d1, float& d2, float& d3,
                                         uint32_t a0, uint32_t a1, uint32_t a2, uint32_t a3,
                                         uint32_t b0, uint32_t b1) {
    asm volatile(
        "mma.sync.aligned.m16n8k8.row.col.f32.tf32.tf32.f32 "
        "{%0,%1,%2,%3}, {%4,%5,%6,%7}, {%8,%9}, {%0,%1,%2,%3};"
        : "+f"(d0), "+f"(d1), "+f"(d2), "+f"(d3)
        : "r"(a0), "r"(a1), "r"(a2), "r"(a3), "r"(b0), "r"(b1));
}

__device__ __forceinline__ void mma_f16(float& d0, float& d1, float& d2, float& d3,
                                        uint32_t a0, uint32_t a1, uint32_t a2, uint32_t a3,
                                        uint32_t b0, uint32_t b1) {
    asm volatile(
        "mma.sync.aligned.m16n8k16.row.col.f32.f16.f16.f32 "
        "{%0,%1,%2,%3}, {%4,%5,%6,%7}, {%8,%9}, {%0,%1,%2,%3};"
        : "+f"(d0), "+f"(d1), "+f"(d2), "+f"(d3)
        : "r"(a0), "r"(a1), "r"(a2), "r"(a3), "r"(b0), "r"(b1));
}

__device__ __forceinline__ void cp_async16(void* smem_dst, const void* gsrc) {
    uint32_t d = (uint32_t)__cvta_generic_to_shared(smem_dst);
    asm volatile("cp.async.cg.shared.global [%0], [%1], 16;\n" :: "r"(d), "l"(gsrc));
}
#define CP_COMMIT() asm volatile("cp.async.commit_group;\n" ::: "memory")
#define CP_WAIT0()  asm volatile("cp.async.wait_group 0;\n" ::: "memory")

// ---------------------------------------------------------------------------
// fp16 tensor-core GEMM for the 1x1-conv projections (m16n8k16, fp32 accum).
//   Out[b][m][p] = sum_k W[m][k] * X[b][k][p] + bias[m]
// BM=128, BN=128, BK=32 (2 k16 steps). 256 threads, 8 warps (4m x 2n),
// warp tile 32x64. X staged raw (cp.async) then packed to half2 in smem.
// MODE 0: v-pair (z = s*8+b, 4 M-tiles). MODE 1: fused q+k (z = b).
// ---------------------------------------------------------------------------
#define PKT_STAGE_B  32768                     // 2 x 32 x 128 floats
#define PKT_AB_B     17408                     // 2 x 16 x 136 u32
#define GEMM16_SMEM  (PKT_STAGE_B + 2 * PKT_AB_B)   // 67584

template<int MODE>
__global__ void __launch_bounds__(256)
gemm_fp16(const float* __restrict__ W0, const float* __restrict__ bias0,
          const float* __restrict__ W1, const float* __restrict__ bias1,
          const float* __restrict__ X0, const float* __restrict__ X1,
          float* __restrict__ O0, float* __restrict__ O1)
{
    constexpr int BN = 128, NKT = KDIM / 32;   // 16 k-tiles of 32

    extern __shared__ char dsm[];
    float*    stage = reinterpret_cast<float*>(dsm);                    // [2][32][128]
    uint32_t* As2   = reinterpret_cast<uint32_t*>(dsm + PKT_STAGE_B);   // [2][16][136]
    uint32_t* Bs2   = reinterpret_cast<uint32_t*>(dsm + PKT_STAGE_B + PKT_AB_B);

    const int t = threadIdx.x;
    const int z = blockIdx.z;
    const int b = (MODE == 0) ? (z & 7) : z;
    const int s = (MODE == 0) ? (z >> 3) : 0;
    const int m0 = (MODE == 0) ? blockIdx.y * 128 : 0;
    const int n0 = blockIdx.x * BN;

    const float* Xb = ((MODE == 0 && s == 1) ? X1 : X0) + (size_t)b * KDIM * HWP + n0;

    const int warp = t >> 5, lane = t & 31;
    const int gid = lane >> 2, tig = lane & 3;
    const int wm = warp >> 1, wn = warp & 1;

    float acc[2][8][4];
    #pragma unroll
    for (int mi = 0; mi < 2; mi++)
        #pragma unroll
        for (int ni = 0; ni < 8; ni++)
            #pragma unroll
            for (int r = 0; r < 4; r++) acc[mi][ni][r] = 0.f;

    auto issue_stage = [&](int kt, int buf) {
        #pragma unroll
        for (int i = 0; i < 4; i++) {
            int fb = t + i * 256;
            int krow = fb >> 5, c4 = fb & 31;
            cp_async16(stage + (size_t)buf * 4096 + krow * 128 + c4 * 4,
                       Xb + (size_t)(kt * 32 + krow) * HWP + c4 * 4);
        }
    };
    auto convert_B = [&](int buf) {
        const float* st = stage + (size_t)buf * 4096;
        uint32_t* dst = Bs2 + (size_t)buf * 16 * 136;
        #pragma unroll
        for (int j = 0; j < 8; j++) {
            int idx = t + j * 256;
            int k2 = idx >> 7, n = idx & 127;
            float x0 = st[(2 * k2    ) * 128 + n];
            float x1 = st[(2 * k2 + 1) * 128 + n];
            dst[k2 * 136 + n] = pack_h2(x0, x1);
        }
    };
    auto load_convert_A = [&](int kt, int buf) {
        uint32_t* dst = As2 + (size_t)buf * 16 * 136;
        #pragma unroll
        for (int i = 0; i < 4; i++) {
            int fa = t + i * 256;
            int row = fa >> 3, c4 = fa & 7;
            const float* src;
            if (MODE == 1) {
                src = (row < 64) ? (W0 + (size_t)row * KDIM)
                                 : (W1 + (size_t)(row - 64) * KDIM);
            } else {
                src = W0 + (size_t)(m0 + row) * KDIM;
            }
            float4 f = *reinterpret_cast<const float4*>(src + kt * 32 + c4 * 4);
            dst[(2 * c4    ) * 136 + row] = pack_h2(f.x, f.y);
            dst[(2 * c4 + 1) * 136 + row] = pack_h2(f.z, f.w);
        }
    };

    issue_stage(0, 0); CP_COMMIT();

    for (int kt = 0; kt < NKT; kt++) {
        const int cur = kt & 1;
        CP_WAIT0();
        __syncthreads();                     // stage[cur] visible to all
        if (kt + 1 < NKT) { issue_stage(kt + 1, cur ^ 1); CP_COMMIT(); }
        convert_B(cur);
        load_convert_A(kt, cur);
        __syncthreads();                     // As2/Bs2[cur] ready

        const uint32_t* Ab = As2 + (size_t)cur * 16 * 136;
        const uint32_t* Bb = Bs2 + (size_t)cur * 16 * 136;
        #pragma unroll
        for (int ks = 0; ks < 2; ks++) {
            const int kr = ks * 8;
            uint32_t af[2][4];
            #pragma unroll
            for (int mi = 0; mi < 2; mi++) {
                int m = wm * 32 + mi * 16;
                af[mi][0] = Ab[(kr + tig    ) * 136 + m + gid];
                af[mi][1] = Ab[(kr + tig    ) * 136 + m + gid + 8];
                af[mi][2] = Ab[(kr + tig + 4) * 136 + m + gid];
                af[mi][3] = Ab[(kr + tig + 4) * 136 + m + gid + 8];
            }
            #pragma unroll
            for (int ni = 0; ni < 8; ni++) {
                int n = wn * 64 + ni * 8 + gid;
                uint32_t b0 = Bb[(kr + tig    ) * 136 + n];
                uint32_t b1 = Bb[(kr + tig + 4) * 136 + n];
                #pragma unroll
                for (int mi = 0; mi < 2; mi++)
                    mma_f16(acc[mi][ni][0], acc[mi][ni][1], acc[mi][ni][2], acc[mi][ni][3],
                            af[mi][0], af[mi][1], af[mi][2], af[mi][3], b0, b1);
            }
        }
    }

    // Epilogue (same mapping as tf32 m16n8 layout: c0,c1 rows gid / c2,c3 rows gid+8)
    #pragma unroll
    for (int mi = 0; mi < 2; mi++) {
        int ml = wm * 32 + mi * 16 + gid;
        #pragma unroll
        for (int half = 0; half < 2; half++) {
            int m = m0 + ml + half * 8;
            float bv;
            float* obase;
            if (MODE == 1) {
                if (m < 64) { bv = bias0[m];      obase = O0 + ((size_t)b * 64 + m)        * HWP; }
                else        { bv = bias1[m - 64]; obase = O1 + ((size_t)b * 64 + (m - 64)) * HWP; }
            } else {
                bv = bias0[m];
                float* O = (s == 1) ? O1 : O0;
                obase = O + ((size_t)b * NC + m) * HWP;
            }
            #pragma unroll
            for (int ni = 0; ni < 8; ni++) {
                int n = n0 + wn * 64 + ni * 8 + tig * 2;
                float2 o;
                o.x = acc[mi][ni][half * 2 + 0] + bv;
                o.y = acc[mi][ni][half * 2 + 1] + bv;
                *reinterpret_cast<float2*>(obase + n) = o;
            }
        }
    }
}

// ---------------------------------------------------------------------------
// energy_H / energy_W / softmax (unchanged)
// ---------------------------------------------------------------------------
__global__ void energy_H_kernel(const float* __restrict__ q,
                                const float* __restrict__ k,
                                float* __restrict__ att)
{
    const int w = blockIdx.x, b = blockIdx.y;
    __shared__ float Qs[64][65];
    __shared__ float Ks[64][65];
    const int t = threadIdx.x;
    #pragma unroll
    for (int i = 0; i < 16; i++) {
        int idx = t + i * 256;
        int c = idx >> 6, h = idx & 63;
        size_t g = ((size_t)(b * NCQ + c) * NH + h) * NW + w;
        Qs[c][h] = q[g];
        Ks[c][h] = k[g];
    }
    __syncthreads();
    const int tx = t & 15, ty = t >> 4;
    float acc[4][4];
    #pragma unroll
    for (int i = 0; i < 4; i++)
        #pragma unroll
        for (int j = 0; j < 4; j++) acc[i][j] = 0.f;
    for (int c = 0; c < 64; c++) {
        float qa[4], kb[4];
        #pragma unroll
        for (int i = 0; i < 4; i++) qa[i] = Qs[c][ty * 4 + i];
        #pragma unroll
        for (int j = 0; j < 4; j++) kb[j] = Ks[c][tx * 4 + j];
        #pragma unroll
        for (int i = 0; i < 4; i++)
            #pragma unroll
            for (int j = 0; j < 4; j++) acc[i][j] += qa[i] * kb[j];
    }
    #pragma unroll
    for (int i = 0; i < 4; i++) {
        int h = ty * 4 + i;
        float4 o = {acc[i][0], acc[i][1], acc[i][2], acc[i][3]};
        *reinterpret_cast<float4*>(&att[((size_t)(b * NH + h) * NW + w) * 128 + tx * 4]) = o;
    }
}

__global__ void energy_W_kernel(const float* __restrict__ q,
                                const float* __restrict__ k,
                                float* __restrict__ att)
{
    const int h = blockIdx.x, b = blockIdx.y;
    __shared__ float Qs[64][65];
    __shared__ float Ks[64][65];
    const int t = threadIdx.x;
    #pragma unroll
    for (int i = 0; i < 16; i++) {
        int idx = t + i * 256;
        int c = idx >> 6, w = idx & 63;
        size_t g = ((size_t)(b * NCQ + c) * NH + h) * NW + w;
        Qs[c][w] = q[g];
        Ks[c][w] = k[g];
    }
    __syncthreads();
    const int tx = t & 15, ty = t >> 4;
    float acc[4][4];
    #pragma unroll
    for (int i = 0; i < 4; i++)
        #pragma unroll
        for (int j = 0; j < 4; j++) acc[i][j] = 0.f;
    for (int c = 0; c < 64; c++) {
        float qa[4], kb[4];
        #pragma unroll
        for (int i = 0; i < 4; i++) qa[i] = Qs[c][ty * 4 + i];
        #pragma unroll
        for (int j = 0; j < 4; j++) kb[j] = Ks[c][tx * 4 + j];
        #pragma unroll
        for (int i = 0; i < 4; i++)
            #pragma unroll
            for (int j = 0; j < 4; j++) acc[i][j] += qa[i] * kb[j];
    }
    #pragma unroll
    for (int i = 0; i < 4; i++) {
        int w = ty * 4 + i;
        float4 o = {acc[i][0], acc[i][1], acc[i][2], acc[i][3]};
        *reinterpret_cast<float4*>(&att[((size_t)(b * NH + h) * NW + w) * 128 + 64 + tx * 4]) = o;
    }
}

__global__ void softmax_kernel(float* __restrict__ att)
{
    int gwarp = (blockIdx.x * blockDim.x + threadIdx.x) >> 5;
    int lane  = threadIdx.x & 31;
    if (gwarp >= NB * HWP) return;
    float4* row = reinterpret_cast<float4*>(att) + (size_t)gwarp * 32;
    float4 v = row[lane];
    float m = fmaxf(fmaxf(v.x, v.y), fmaxf(v.z, v.w));
    #pragma unroll
    for (int o = 16; o > 0; o >>= 1) m = fmaxf(m, __shfl_xor_sync(0xFFFFFFFFu, m, o));
    v.x = __expf(v.x - m); v.y = __expf(v.y - m);
    v.z = __expf(v.z - m); v.w = __expf(v.w - m);
    float s = v.x + v.y + v.z + v.w;
    #pragma unroll
    for (int o = 16; o > 0; o >>= 1) s += __shfl_xor_sync(0xFFFFFFFFu, s, o);
    float r = 1.0f / s;
    v.x *= r; v.y *= r; v.z *= r; v.w *= r;
    row[lane] = v;
}

// ---------------------------------------------------------------------------
// aggH_mma: tf32 mma with RAW fp32 bits (HW truncates to tf32; no cvt ops).
// ---------------------------------------------------------------------------
#define VS_PITCH 517
#define AS_PITCH 68
__global__ void __launch_bounds__(256)
aggH_mma(const float* __restrict__ v2, const float* __restrict__ v1,
         const float* __restrict__ x2, const float* __restrict__ x1,
         const float* __restrict__ att, const float* __restrict__ gamma,
         float* __restrict__ y)
{
    extern __shared__ uint32_t sm[];
    uint32_t* Vs = sm;
    float*    AsF = reinterpret_cast<float*>(sm + 32 * VS_PITCH);

    const int t  = threadIdx.x;
    const int wg = blockIdx.x;
    const int cs = blockIdx.y;
    const int b  = blockIdx.z;
    const int s  = cs >> 4;
    const int cBase = (cs & 15) * 32;
    const int w0 = wg * 8;

    const float* v = (s == 1) ? v1 : v2;
    const float* x = (s == 1) ? x1 : x2;
    float* yd = y + (size_t)s * NB * NC * HWP;
    const float g = gamma[0];

    auto issue_att = [&](int w, int buf) {
        #pragma unroll
        for (int i = 0; i < 4; i++) {
            int f = t + i * 256;
            int h = f >> 4, q = f & 15;
            cp_async16(AsF + (size_t)buf * 64 * AS_PITCH + h * AS_PITCH + q * 4,
                       att + ((size_t)(b * NH + h) * NW + (w0 + w)) * 128 + q * 4);
        }
    };

    issue_att(0, 0); CP_COMMIT();

    #pragma unroll
    for (int i = 0; i < 8; i++) {
        int rr = t + i * 256;
        int ci = rr >> 6, hp = rr & 63;
        const float* src = v + ((size_t)(b * NC + cBase + ci) * NH + hp) * NW + w0;
        uint4 u0 = *reinterpret_cast<const uint4*>(src);
        uint4 u1 = *reinterpret_cast<const uint4*>(src + 4);
        uint32_t* d = Vs + ci * VS_PITCH + hp * 8;
        d[0] = u0.x; d[1] = u0.y; d[2] = u0.z; d[3] = u0.w;
        d[4] = u1.x; d[5] = u1.y; d[6] = u1.z; d[7] = u1.w;
    }
    CP_WAIT0();
    __syncthreads();

    const int warp = t >> 5, lane = t & 31;
    const int gid = lane >> 2, tig = lane & 3;
    const int mi = warp >> 1;
    const int nh = warp & 1;

    float acc[8][2][4];
    #pragma unroll
    for (int w = 0; w < 8; w++)
        #pragma unroll
        for (int ni = 0; ni < 2; ni++)
            #pragma unroll
            for (int r = 0; r < 4; r++) acc[w][ni][r] = 0.f;

    for (int w = 0; w < 8; w++) {
        const int cur = w & 1;
        if (w + 1 < 8) { issue_att(w + 1, cur ^ 1); CP_COMMIT(); }

        const uint32_t* Ac = reinterpret_cast<const uint32_t*>(AsF + (size_t)cur * 64 * AS_PITCH);
        #pragma unroll
        for (int k = 0; k < 8; k++) {
            const int k0 = k * 8;
            const int m = mi * 16;
            uint32_t a0 = Ac[(m + gid    ) * AS_PITCH + k0 + tig    ];
            uint32_t a1 = Ac[(m + gid + 8) * AS_PITCH + k0 + tig    ];
            uint32_t a2 = Ac[(m + gid    ) * AS_PITCH + k0 + tig + 4];
            uint32_t a3 = Ac[(m + gid + 8) * AS_PITCH + k0 + tig + 4];
            #pragma unroll
            for (int ni = 0; ni < 2; ni++) {
                int n = nh * 16 + ni * 8 + gid;
                uint32_t b0 = Vs[n * VS_PITCH + (k0 + tig    ) * 8 + w];
                uint32_t b1 = Vs[n * VS_PITCH + (k0 + tig + 4) * 8 + w];
                mma_tf32(acc[w][ni][0], acc[w][ni][1], acc[w][ni][2], acc[w][ni][3],
                         a0, a1, a2, a3, b0, b1);
            }
        }
        if (w + 1 < 8) { CP_WAIT0(); __syncthreads(); }
    }

    #pragma unroll
    for (int ni = 0; ni < 2; ni++) {
        #pragma unroll
        for (int rh = 0; rh < 2; rh++) {
            #pragma unroll
            for (int cp = 0; cp < 2; cp++) {
                int h = mi * 16 + gid + rh * 8;
                int c = cBase + nh * 16 + ni * 8 + tig * 2 + cp;
                size_t base = ((size_t)(b * NC + c) * NH + h) * NW + w0;
                float4 xa = *reinterpret_cast<const float4*>(x + base);
                float4 xb = *reinterpret_cast<const float4*>(x + base + 4);
                float4 oa, ob;
                oa.x = xa.x + g * acc[0][ni][rh * 2 + cp];
                oa.y = xa.y + g * acc[1][ni][rh * 2 + cp];
                oa.z = xa.z + g * acc[2][ni][rh * 2 + cp];
                oa.w = xa.w + g * acc[3][ni][rh * 2 + cp];
                ob.x = xb.x + g * acc[4][ni][rh * 2 + cp];
                ob.y = xb.y + g * acc[5][ni][rh * 2 + cp];
                ob.z = xb.z + g * acc[6][ni][rh * 2 + cp];
                ob.w = xb.w + g * acc[7][ni][rh * 2 + cp];
                *reinterpret_cast<float4*>(yd + base)     = oa;
                *reinterpret_cast<float4*>(yd + base + 4) = ob;
            }
        }
    }
}

// ---------------------------------------------------------------------------
// aggW_mma: tf32 mma, raw fp32 bits (no cvt).
// ---------------------------------------------------------------------------
__global__ void __launch_bounds__(256)
aggW_mma(const float* __restrict__ v2, const float* __restrict__ v1,
         const float* __restrict__ att, const float* __restrict__ gamma,
         float* __restrict__ y)
{
    __shared__ uint32_t As[64 * 66];
    __shared__ uint32_t Vs[64 * 66];

    const int t  = threadIdx.x;
    const int h  = blockIdx.x;
    const int cs = blockIdx.y;
    const int b  = blockIdx.z;
    const int s  = cs >> 3;
    const int cBase = (cs & 7) * 64;

    const float* v = (s == 1) ? v1 : v2;
    float* yd = y + (size_t)s * NB * NC * HWP;
    const float g = gamma[0];

    #pragma unroll
    for (int i = 0; i < 4; i++) {
        int f = t + i * 256;
        int r = f >> 4, q = f & 15;
        const uint4 ua = *reinterpret_cast<const uint4*>(
            att + ((size_t)(b * NH + h) * NW + r) * 128 + 64 + q * 4);
        uint32_t* da = As + r * 66 + q * 4;
        da[0] = ua.x; da[1] = ua.y; da[2] = ua.z; da[3] = ua.w;
        const uint4 uv = *reinterpret_cast<const uint4*>(
            v + ((size_t)(b * NC + cBase + r) * NH + h) * NW + q * 4);
        uint32_t* dv = Vs + r * 66 + q * 4;
        dv[0] = uv.x; dv[1] = uv.y; dv[2] = uv.z; dv[3] = uv.w;
    }
    __syncthreads();

    const int warp = t >> 5, lane = t & 31;
    const int gid = lane >> 2, tig = lane & 3;
    const int mi = warp >> 1;
    const int nh = warp & 1;

    float acc[4][4];
    #pragma unroll
    for (int ni = 0; ni < 4; ni++)
        #pragma unroll
        for (int r = 0; r < 4; r++) acc[ni][r] = 0.f;

    #pragma unroll
    for (int k = 0; k < 8; k++) {
        const int k0 = k * 8;
        const int m = mi * 16;
        uint32_t a0 = As[(m + gid    ) * 66 + k0 + tig    ];
        uint32_t a1 = As[(m + gid + 8) * 66 + k0 + tig    ];
        uint32_t a2 = As[(m + gid    ) * 66 + k0 + tig + 4];
        uint32_t a3 = As[(m + gid + 8) * 66 + k0 + tig + 4];
        #pragma unroll
        for (int ni = 0; ni < 4; ni++) {
            int n = nh * 32 + ni * 8 + gid;
            uint32_t b0 = Vs[n * 66 + k0 + tig    ];
            uint32_t b1 = Vs[n * 66 + k0 + tig + 4];
            mma_tf32(acc[ni][0], acc[ni][1], acc[ni][2], acc[ni][3],
                     a0, a1, a2, a3, b0, b1);
        }
    }

    #pragma unroll
    for (int ni = 0; ni < 4; ni++) {
        #pragma unroll
        for (int rh = 0; rh < 2; rh++) {
            int w = mi * 16 + gid + rh * 8;
            #pragma unroll
            for (int cp = 0; cp < 2; cp++) {
                int c = cBase + nh * 32 + ni * 8 + tig * 2 + cp;
                size_t idx = ((size_t)(b * NC + c) * NH + h) * NW + w;
                yd[idx] += g * acc[ni][rh * 2 + cp];
            }
        }
    }
}

// ---------------------------------------------------------------------------
extern "C" void kernel_launch(void* const* d_in, const int* in_sizes, int n_in,
                              void* d_out, int out_size)
{
    const float* x2    = (const float*)d_in[0];
    const float* x1    = (const float*)d_in[1];
    const float* q_w   = (const float*)d_in[2];
    const float* q_b   = (const float*)d_in[3];
    const float* k_w   = (const float*)d_in[4];
    const float* k_b   = (const float*)d_in[5];
    const float* v_w   = (const float*)d_in[6];
    const float* v_b   = (const float*)d_in[7];
    const float* gamma = (const float*)d_in[8];
    float* y = (float*)d_out;

    float *gq, *gk, *gv2, *gv1, *gatt;
    cudaGetSymbolAddress((void**)&gq,  g_q);
    cudaGetSymbolAddress((void**)&gk,  g_k);
    cudaGetSymbolAddress((void**)&gv2, g_v2);
    cudaGetSymbolAddress((void**)&gv1, g_v1);
    cudaGetSymbolAddress((void**)&gatt, g_att);

    const int aggH_smem = (32 * VS_PITCH + 2 * 64 * AS_PITCH) * 4;
    cudaFuncSetAttribute(aggH_mma, cudaFuncAttributeMaxDynamicSharedMemorySize, aggH_smem);
    cudaFuncSetAttribute(gemm_fp16<0>, cudaFuncAttributeMaxDynamicSharedMemorySize, GEMM16_SMEM);
    cudaFuncSetAttribute(gemm_fp16<1>, cudaFuncAttributeMaxDynamicSharedMemorySize, GEMM16_SMEM);

    gemm_fp16<1><<<dim3(32, 1, 8),  256, GEMM16_SMEM>>>(q_w, q_b, k_w, k_b, x2, nullptr, gq, gk);
    energy_H_kernel<<<dim3(NW, NB), 256>>>(gq, gk, gatt);
    energy_W_kernel<<<dim3(NH, NB), 256>>>(gq, gk, gatt);
    gemm_fp16<0><<<dim3(32, 4, 16), 256, GEMM16_SMEM>>>(v_w, v_b, nullptr, nullptr, x2, x1, gv2, gv1);
    softmax_kernel<<<(NB * HWP) / 8, 256>>>(gatt);
    aggH_mma<<<dim3(8, 32, NB), 256, aggH_smem>>>(gv2, gv1, x2, x1, gatt, gamma, y);
    aggW_mma<<<dim3(NH, 16, NB), 256>>>(gv2, gv1, gatt, gamma, y);
}

// round 7
// speedup vs baseline: 3.2910x; 1.1063x over previous
#include <cuda_runtime.h>
#include <cuda_fp16.h>
#include <cstddef>
#include <cstdint>

// Problem constants
#define NB 8
#define NC 512
#define NH 64
#define NW 64
#define NCQ 64
#define HWP 4096   // NH*NW
#define KDIM 512

// Scratch (statically allocated device globals; no cudaMalloc allowed)
__device__ float g_q  [NB * NCQ * HWP];
__device__ float g_k  [NB * NCQ * HWP];
__device__ float g_v2 [NB * NC  * HWP];
__device__ float g_v1 [NB * NC  * HWP];
__device__ float g_att[NB * HWP * 128];
__device__ uint32_t g_whv [256 * 512];   // v_w as half2 pairs, [k2][m]
__device__ uint32_t g_whqk[256 * 128];   // q_w(0:64)+k_w(64:128) as half2, [k2][m]

__device__ __forceinline__ uint32_t pack_h2(float a, float b) {
    __half2 h = __floats2half2_rn(a, b);
    return *reinterpret_cast<uint32_t*>(&h);
}

__device__ __forceinline__ void mma_tf32(float& d0, float& d1, float& d2, float& d3,
                                         uint32_t a0, uint32_t a1, uint32_t a2, uint32_t a3,
                                         uint32_t b0, uint32_t b1) {
    asm volatile(
        "mma.sync.aligned.m16n8k8.row.col.f32.tf32.tf32.f32 "
        "{%0,%1,%2,%3}, {%4,%5,%6,%7}, {%8,%9}, {%0,%1,%2,%3};"
        : "+f"(d0), "+f"(d1), "+f"(d2), "+f"(d3)
        : "r"(a0), "r"(a1), "r"(a2), "r"(a3), "r"(b0), "r"(b1));
}

__device__ __forceinline__ void mma_f16(float& d0, float& d1, float& d2, float& d3,
                                        uint32_t a0, uint32_t a1, uint32_t a2, uint32_t a3,
                                        uint32_t b0, uint32_t b1) {
    asm volatile(
        "mma.sync.aligned.m16n8k16.row.col.f32.f16.f16.f32 "
        "{%0,%1,%2,%3}, {%4,%5,%6,%7}, {%8,%9}, {%0,%1,%2,%3};"
        : "+f"(d0), "+f"(d1), "+f"(d2), "+f"(d3)
        : "r"(a0), "r"(a1), "r"(a2), "r"(a3), "r"(b0), "r"(b1));
}

__device__ __forceinline__ void cp_async16(void* smem_dst, const void* gsrc) {
    uint32_t d = (uint32_t)__cvta_generic_to_shared(smem_dst);
    asm volatile("cp.async.cg.shared.global [%0], [%1], 16;\n" :: "r"(d), "l"(gsrc));
}
#define CP_COMMIT() asm volatile("cp.async.commit_group;\n" ::: "memory")
#define CP_WAIT0()  asm volatile("cp.async.wait_group 0;\n" ::: "memory")

// ---------------------------------------------------------------------------
// preconv: pack weights to half2 [k2][m] layout (one-time, ~1MB).
//   g_whv [k2*512+m] = half2(v_w[m][2k2], v_w[m][2k2+1])
//   g_whqk[k2*128+m] = q rows 0-63, k rows 64-127
// ---------------------------------------------------------------------------
__global__ void preconv(const float* __restrict__ vw,
                        const float* __restrict__ qw,
                        const float* __restrict__ kw)
{
    int idx = blockIdx.x * 256 + threadIdx.x;
    if (idx < 512 * 256) {
        int m = idx >> 8, k2 = idx & 255;
        g_whv[k2 * 512 + m] = pack_h2(vw[(size_t)m * KDIM + 2 * k2],
                                      vw[(size_t)m * KDIM + 2 * k2 + 1]);
    } else {
        int r = idx - 512 * 256;      // 0 .. 128*256-1
        int m = r >> 8, k2 = r & 255;
        const float* src = (m < 64) ? (qw + (size_t)m * KDIM)
                                    : (kw + (size_t)(m - 64) * KDIM);
        g_whqk[k2 * 128 + m] = pack_h2(src[2 * k2], src[2 * k2 + 1]);
    }
}

// ---------------------------------------------------------------------------
// gemm_all: all projections, fp16 mma (m16n8k16, fp32 accum).
// z<16: v-pair (b=z&7, s=z>>3, m-tile=y). z>=16: fused q+k (b=z-16, y==0 only).
// A tile: pure cp.async from pre-packed weights. B tile: LDG float4 pairs ->
// register pack -> single uint4 STS. Double-buffered smem, reg-prefetched B.
// ---------------------------------------------------------------------------
__global__ void __launch_bounds__(256)
gemm_all(const float* __restrict__ vb, const float* __restrict__ qb,
         const float* __restrict__ kb,
         const float* __restrict__ x2, const float* __restrict__ x1,
         float* __restrict__ gv2, float* __restrict__ gv1,
         float* __restrict__ gq,  float* __restrict__ gk)
{
    constexpr int NKT = KDIM / 32;   // 16 k-tiles of 32

    __shared__ alignas(16) uint32_t As2[2][16][136];
    __shared__ alignas(16) uint32_t Bs2[2][16][136];

    const int t = threadIdx.x;
    const int z = blockIdx.z;
    const bool qkm = (z >= 16);
    if (qkm && blockIdx.y != 0) return;
    const int b = qkm ? (z - 16) : (z & 7);
    const int s = qkm ? 0 : (z >> 3);
    const int m0 = qkm ? 0 : blockIdx.y * 128;
    const int n0 = blockIdx.x * 128;

    const float* Xb = (qkm ? x2 : (s ? x1 : x2)) + (size_t)b * KDIM * HWP + n0;
    const uint32_t* Wh = qkm ? g_whqk : g_whv;
    const int wpitch = qkm ? 128 : 512;

    const int warp = t >> 5, lane = t & 31;
    const int gid = lane >> 2, tig = lane & 3;
    const int wm = warp >> 1, wn = warp & 1;

    float acc[2][8][4];
    #pragma unroll
    for (int mi = 0; mi < 2; mi++)
        #pragma unroll
        for (int ni = 0; ni < 8; ni++)
            #pragma unroll
            for (int r = 0; r < 4; r++) acc[mi][ni][r] = 0.f;

    float4 pb[2][2];

    auto issueA = [&](int kt, int buf) {
        #pragma unroll
        for (int i = 0; i < 2; i++) {
            int fa = t + i * 256;
            int k2r = fa >> 5, m4 = fa & 31;
            cp_async16(&As2[buf][k2r][m4 * 4],
                       Wh + (size_t)(kt * 16 + k2r) * wpitch + m0 + m4 * 4);
        }
    };
    auto loadB = [&](int kt) {
        #pragma unroll
        for (int i = 0; i < 2; i++) {
            int fb = t + i * 256;
            int k2 = fb >> 5, n4 = fb & 31;
            const float* base = Xb + (size_t)(kt * 32 + 2 * k2) * HWP + n4 * 4;
            pb[i][0] = *reinterpret_cast<const float4*>(base);
            pb[i][1] = *reinterpret_cast<const float4*>(base + HWP);
        }
    };
    auto storeB = [&](int buf) {
        #pragma unroll
        for (int i = 0; i < 2; i++) {
            int fb = t + i * 256;
            int k2 = fb >> 5, n4 = fb & 31;
            uint4 u;
            u.x = pack_h2(pb[i][0].x, pb[i][1].x);
            u.y = pack_h2(pb[i][0].y, pb[i][1].y);
            u.z = pack_h2(pb[i][0].z, pb[i][1].z);
            u.w = pack_h2(pb[i][0].w, pb[i][1].w);
            *reinterpret_cast<uint4*>(&Bs2[buf][k2][n4 * 4]) = u;
        }
    };

    issueA(0, 0); CP_COMMIT();
    loadB(0); storeB(0);
    CP_WAIT0();
    __syncthreads();

    for (int kt = 0; kt < NKT; kt++) {
        const int cur = kt & 1;
        if (kt + 1 < NKT) { issueA(kt + 1, cur ^ 1); CP_COMMIT(); loadB(kt + 1); }

        #pragma unroll
        for (int ks = 0; ks < 2; ks++) {
            const int kr = ks * 8;
            uint32_t af[2][4];
            #pragma unroll
            for (int mi = 0; mi < 2; mi++) {
                int m = wm * 32 + mi * 16;
                af[mi][0] = As2[cur][kr + tig    ][m + gid];
                af[mi][1] = As2[cur][kr + tig    ][m + gid + 8];
                af[mi][2] = As2[cur][kr + tig + 4][m + gid];
                af[mi][3] = As2[cur][kr + tig + 4][m + gid + 8];
            }
            #pragma unroll
            for (int ni = 0; ni < 8; ni++) {
                int n = wn * 64 + ni * 8 + gid;
                uint32_t b0 = Bs2[cur][kr + tig    ][n];
                uint32_t b1 = Bs2[cur][kr + tig + 4][n];
                #pragma unroll
                for (int mi = 0; mi < 2; mi++)
                    mma_f16(acc[mi][ni][0], acc[mi][ni][1], acc[mi][ni][2], acc[mi][ni][3],
                            af[mi][0], af[mi][1], af[mi][2], af[mi][3], b0, b1);
            }
        }

        if (kt + 1 < NKT) { storeB(cur ^ 1); CP_WAIT0(); __syncthreads(); }
    }

    #pragma unroll
    for (int mi = 0; mi < 2; mi++) {
        int ml = wm * 32 + mi * 16 + gid;
        #pragma unroll
        for (int half = 0; half < 2; half++) {
            int m = m0 + ml + half * 8;
            float bv;
            float* obase;
            if (qkm) {
                if (m < 64) { bv = qb[m];      obase = gq + ((size_t)b * 64 + m)        * HWP; }
                else        { bv = kb[m - 64]; obase = gk + ((size_t)b * 64 + (m - 64)) * HWP; }
            } else {
                bv = vb[m];
                float* O = s ? gv1 : gv2;
                obase = O + ((size_t)b * NC + m) * HWP;
            }
            #pragma unroll
            for (int ni = 0; ni < 8; ni++) {
                int n = n0 + wn * 64 + ni * 8 + tig * 2;
                float2 o;
                o.x = acc[mi][ni][half * 2 + 0] + bv;
                o.y = acc[mi][ni][half * 2 + 1] + bv;
                *reinterpret_cast<float2*>(obase + n) = o;
            }
        }
    }
}

// ---------------------------------------------------------------------------
// energy_HW: fused energy_H (y==0) and energy_W (y==1).
// ---------------------------------------------------------------------------
__global__ void energy_HW(const float* __restrict__ q,
                          const float* __restrict__ k,
                          float* __restrict__ att)
{
    __shared__ float Qs[64][65];
    __shared__ float Ks[64][65];
    const int t = threadIdx.x;
    const int b = blockIdx.z;
    const int tx = t & 15, ty = t >> 4;

    if (blockIdx.y == 0) {
        const int w = blockIdx.x;
        #pragma unroll
        for (int i = 0; i < 16; i++) {
            int idx = t + i * 256;
            int c = idx >> 6, h = idx & 63;
            size_t g = ((size_t)(b * NCQ + c) * NH + h) * NW + w;
            Qs[c][h] = q[g];
            Ks[c][h] = k[g];
        }
        __syncthreads();
        float acc[4][4];
        #pragma unroll
        for (int i = 0; i < 4; i++)
            #pragma unroll
            for (int j = 0; j < 4; j++) acc[i][j] = 0.f;
        for (int c = 0; c < 64; c++) {
            float qa[4], kb[4];
            #pragma unroll
            for (int i = 0; i < 4; i++) qa[i] = Qs[c][ty * 4 + i];
            #pragma unroll
            for (int j = 0; j < 4; j++) kb[j] = Ks[c][tx * 4 + j];
            #pragma unroll
            for (int i = 0; i < 4; i++)
                #pragma unroll
                for (int j = 0; j < 4; j++) acc[i][j] += qa[i] * kb[j];
        }
        #pragma unroll
        for (int i = 0; i < 4; i++) {
            int h = ty * 4 + i;
            float4 o = {acc[i][0], acc[i][1], acc[i][2], acc[i][3]};
            *reinterpret_cast<float4*>(&att[((size_t)(b * NH + h) * NW + w) * 128 + tx * 4]) = o;
        }
    } else {
        const int h = blockIdx.x;
        #pragma unroll
        for (int i = 0; i < 16; i++) {
            int idx = t + i * 256;
            int c = idx >> 6, w = idx & 63;
            size_t g = ((size_t)(b * NCQ + c) * NH + h) * NW + w;
            Qs[c][w] = q[g];
            Ks[c][w] = k[g];
        }
        __syncthreads();
        float acc[4][4];
        #pragma unroll
        for (int i = 0; i < 4; i++)
            #pragma unroll
            for (int j = 0; j < 4; j++) acc[i][j] = 0.f;
        for (int c = 0; c < 64; c++) {
            float qa[4], kb[4];
            #pragma unroll
            for (int i = 0; i < 4; i++) qa[i] = Qs[c][ty * 4 + i];
            #pragma unroll
            for (int j = 0; j < 4; j++) kb[j] = Ks[c][tx * 4 + j];
            #pragma unroll
            for (int i = 0; i < 4; i++)
                #pragma unroll
                for (int j = 0; j < 4; j++) acc[i][j] += qa[i] * kb[j];
        }
        #pragma unroll
        for (int i = 0; i < 4; i++) {
            int w = ty * 4 + i;
            float4 o = {acc[i][0], acc[i][1], acc[i][2], acc[i][3]};
            *reinterpret_cast<float4*>(&att[((size_t)(b * NH + h) * NW + w) * 128 + 64 + tx * 4]) = o;
        }
    }
}

// ---------------------------------------------------------------------------
// softmax (unchanged)
// ---------------------------------------------------------------------------
__global__ void softmax_kernel(float* __restrict__ att)
{
    int gwarp = (blockIdx.x * blockDim.x + threadIdx.x) >> 5;
    int lane  = threadIdx.x & 31;
    if (gwarp >= NB * HWP) return;
    float4* row = reinterpret_cast<float4*>(att) + (size_t)gwarp * 32;
    float4 v = row[lane];
    float m = fmaxf(fmaxf(v.x, v.y), fmaxf(v.z, v.w));
    #pragma unroll
    for (int o = 16; o > 0; o >>= 1) m = fmaxf(m, __shfl_xor_sync(0xFFFFFFFFu, m, o));
    v.x = __expf(v.x - m); v.y = __expf(v.y - m);
    v.z = __expf(v.z - m); v.w = __expf(v.w - m);
    float s = v.x + v.y + v.z + v.w;
    #pragma unroll
    for (int o = 16; o > 0; o >>= 1) s += __shfl_xor_sync(0xFFFFFFFFu, s, o);
    float r = 1.0f / s;
    v.x *= r; v.y *= r; v.z *= r; v.w *= r;
    row[lane] = v;
}

// ---------------------------------------------------------------------------
// aggH_mma (unchanged from R6: tf32 mma, raw fp32 bits)
// ---------------------------------------------------------------------------
#define VS_PITCH 517
#define AS_PITCH 68
__global__ void __launch_bounds__(256)
aggH_mma(const float* __restrict__ v2, const float* __restrict__ v1,
         const float* __restrict__ x2, const float* __restrict__ x1,
         const float* __restrict__ att, const float* __restrict__ gamma,
         float* __restrict__ y)
{
    extern __shared__ uint32_t sm[];
    uint32_t* Vs = sm;
    float*    AsF = reinterpret_cast<float*>(sm + 32 * VS_PITCH);

    const int t  = threadIdx.x;
    const int wg = blockIdx.x;
    const int cs = blockIdx.y;
    const int b  = blockIdx.z;
    const int s  = cs >> 4;
    const int cBase = (cs & 15) * 32;
    const int w0 = wg * 8;

    const float* v = (s == 1) ? v1 : v2;
    const float* x = (s == 1) ? x1 : x2;
    float* yd = y + (size_t)s * NB * NC * HWP;
    const float g = gamma[0];

    auto issue_att = [&](int w, int buf) {
        #pragma unroll
        for (int i = 0; i < 4; i++) {
            int f = t + i * 256;
            int h = f >> 4, q = f & 15;
            cp_async16(AsF + (size_t)buf * 64 * AS_PITCH + h * AS_PITCH + q * 4,
                       att + ((size_t)(b * NH + h) * NW + (w0 + w)) * 128 + q * 4);
        }
    };

    issue_att(0, 0); CP_COMMIT();

    #pragma unroll
    for (int i = 0; i < 8; i++) {
        int rr = t + i * 256;
        int ci = rr >> 6, hp = rr & 63;
        const float* src = v + ((size_t)(b * NC + cBase + ci) * NH + hp) * NW + w0;
        uint4 u0 = *reinterpret_cast<const uint4*>(src);
        uint4 u1 = *reinterpret_cast<const uint4*>(src + 4);
        uint32_t* d = Vs + ci * VS_PITCH + hp * 8;
        d[0] = u0.x; d[1] = u0.y; d[2] = u0.z; d[3] = u0.w;
        d[4] = u1.x; d[5] = u1.y; d[6] = u1.z; d[7] = u1.w;
    }
    CP_WAIT0();
    __syncthreads();

    const int warp = t >> 5, lane = t & 31;
    const int gid = lane >> 2, tig = lane & 3;
    const int mi = warp >> 1;
    const int nh = warp & 1;

    float acc[8][2][4];
    #pragma unroll
    for (int w = 0; w < 8; w++)
        #pragma unroll
        for (int ni = 0; ni < 2; ni++)
            #pragma unroll
            for (int r = 0; r < 4; r++) acc[w][ni][r] = 0.f;

    for (int w = 0; w < 8; w++) {
        const int cur = w & 1;
        if (w + 1 < 8) { issue_att(w + 1, cur ^ 1); CP_COMMIT(); }

        const uint32_t* Ac = reinterpret_cast<const uint32_t*>(AsF + (size_t)cur * 64 * AS_PITCH);
        #pragma unroll
        for (int k = 0; k < 8; k++) {
            const int k0 = k * 8;
            const int m = mi * 16;
            uint32_t a0 = Ac[(m + gid    ) * AS_PITCH + k0 + tig    ];
            uint32_t a1 = Ac[(m + gid + 8) * AS_PITCH + k0 + tig    ];
            uint32_t a2 = Ac[(m + gid    ) * AS_PITCH + k0 + tig + 4];
            uint32_t a3 = Ac[(m + gid + 8) * AS_PITCH + k0 + tig + 4];
            #pragma unroll
            for (int ni = 0; ni < 2; ni++) {
                int n = nh * 16 + ni * 8 + gid;
                uint32_t b0 = Vs[n * VS_PITCH + (k0 + tig    ) * 8 + w];
                uint32_t b1 = Vs[n * VS_PITCH + (k0 + tig + 4) * 8 + w];
                mma_tf32(acc[w][ni][0], acc[w][ni][1], acc[w][ni][2], acc[w][ni][3],
                         a0, a1, a2, a3, b0, b1);
            }
        }
        if (w + 1 < 8) { CP_WAIT0(); __syncthreads(); }
    }

    #pragma unroll
    for (int ni = 0; ni < 2; ni++) {
        #pragma unroll
        for (int rh = 0; rh < 2; rh++) {
            #pragma unroll
            for (int cp = 0; cp < 2; cp++) {
                int h = mi * 16 + gid + rh * 8;
                int c = cBase + nh * 16 + ni * 8 + tig * 2 + cp;
                size_t base = ((size_t)(b * NC + c) * NH + h) * NW + w0;
                float4 xa = *reinterpret_cast<const float4*>(x + base);
                float4 xb = *reinterpret_cast<const float4*>(x + base + 4);
                float4 oa, ob;
                oa.x = xa.x + g * acc[0][ni][rh * 2 + cp];
                oa.y = xa.y + g * acc[1][ni][rh * 2 + cp];
                oa.z = xa.z + g * acc[2][ni][rh * 2 + cp];
                oa.w = xa.w + g * acc[3][ni][rh * 2 + cp];
                ob.x = xb.x + g * acc[4][ni][rh * 2 + cp];
                ob.y = xb.y + g * acc[5][ni][rh * 2 + cp];
                ob.z = xb.z + g * acc[6][ni][rh * 2 + cp];
                ob.w = xb.w + g * acc[7][ni][rh * 2 + cp];
                *reinterpret_cast<float4*>(yd + base)     = oa;
                *reinterpret_cast<float4*>(yd + base + 4) = ob;
            }
        }
    }
}

// ---------------------------------------------------------------------------
// aggW_mma (unchanged from R6)
// ---------------------------------------------------------------------------
__global__ void __launch_bounds__(256)
aggW_mma(const float* __restrict__ v2, const float* __restrict__ v1,
         const float* __restrict__ att, const float* __restrict__ gamma,
         float* __restrict__ y)
{
    __shared__ uint32_t As[64 * 66];
    __shared__ uint32_t Vs[64 * 66];

    const int t  = threadIdx.x;
    const int h  = blockIdx.x;
    const int cs = blockIdx.y;
    const int b  = blockIdx.z;
    const int s  = cs >> 3;
    const int cBase = (cs & 7) * 64;

    const float* v = (s == 1) ? v1 : v2;
    float* yd = y + (size_t)s * NB * NC * HWP;
    const float g = gamma[0];

    #pragma unroll
    for (int i = 0; i < 4; i++) {
        int f = t + i * 256;
        int r = f >> 4, q = f & 15;
        const uint4 ua = *reinterpret_cast<const uint4*>(
            att + ((size_t)(b * NH + h) * NW + r) * 128 + 64 + q * 4);
        uint32_t* da = As + r * 66 + q * 4;
        da[0] = ua.x; da[1] = ua.y; da[2] = ua.z; da[3] = ua.w;
        const uint4 uv = *reinterpret_cast<const uint4*>(
            v + ((size_t)(b * NC + cBase + r) * NH + h) * NW + q * 4);
        uint32_t* dv = Vs + r * 66 + q * 4;
        dv[0] = uv.x; dv[1] = uv.y; dv[2] = uv.z; dv[3] = uv.w;
    }
    __syncthreads();

    const int warp = t >> 5, lane = t & 31;
    const int gid = lane >> 2, tig = lane & 3;
    const int mi = warp >> 1;
    const int nh = warp & 1;

    float acc[4][4];
    #pragma unroll
    for (int ni = 0; ni < 4; ni++)
        #pragma unroll
        for (int r = 0; r < 4; r++) acc[ni][r] = 0.f;

    #pragma unroll
    for (int k = 0; k < 8; k++) {
        const int k0 = k * 8;
        const int m = mi * 16;
        uint32_t a0 = As[(m + gid    ) * 66 + k0 + tig    ];
        uint32_t a1 = As[(m + gid + 8) * 66 + k0 + tig    ];
        uint32_t a2 = As[(m + gid    ) * 66 + k0 + tig + 4];
        uint32_t a3 = As[(m + gid + 8) * 66 + k0 + tig + 4];
        #pragma unroll
        for (int ni = 0; ni < 4; ni++) {
            int n = nh * 32 + ni * 8 + gid;
            uint32_t b0 = Vs[n * 66 + k0 + tig    ];
            uint32_t b1 = Vs[n * 66 + k0 + tig + 4];
            mma_tf32(acc[ni][0], acc[ni][1], acc[ni][2], acc[ni][3],
                     a0, a1, a2, a3, b0, b1);
        }
    }

    #pragma unroll
    for (int ni = 0; ni < 4; ni++) {
        #pragma unroll
        for (int rh = 0; rh < 2; rh++) {
            int w = mi * 16 + gid + rh * 8;
            #pragma unroll
            for (int cp = 0; cp < 2; cp++) {
                int c = cBase + nh * 32 + ni * 8 + tig * 2 + cp;
                size_t idx = ((size_t)(b * NC + c) * NH + h) * NW + w;
                yd[idx] += g * acc[ni][rh * 2 + cp];
            }
        }
    }
}

// ---------------------------------------------------------------------------
extern "C" void kernel_launch(void* const* d_in, const int* in_sizes, int n_in,
                              void* d_out, int out_size)
{
    const float* x2    = (const float*)d_in[0];
    const float* x1    = (const float*)d_in[1];
    const float* q_w   = (const float*)d_in[2];
    const float* q_b   = (const float*)d_in[3];
    const float* k_w   = (const float*)d_in[4];
    const float* k_b   = (const float*)d_in[5];
    const float* v_w   = (const float*)d_in[6];
    const float* v_b   = (const float*)d_in[7];
    const float* gamma = (const float*)d_in[8];
    float* y = (float*)d_out;

    float *gq, *gk, *gv2, *gv1, *gatt;
    cudaGetSymbolAddress((void**)&gq,  g_q);
    cudaGetSymbolAddress((void**)&gk,  g_k);
    cudaGetSymbolAddress((void**)&gv2, g_v2);
    cudaGetSymbolAddress((void**)&gv1, g_v1);
    cudaGetSymbolAddress((void**)&gatt, g_att);

    const int aggH_smem = (32 * VS_PITCH + 2 * 64 * AS_PITCH) * 4;
    cudaFuncSetAttribute(aggH_mma, cudaFuncAttributeMaxDynamicSharedMemorySize, aggH_smem);

    preconv<<<640, 256>>>(v_w, q_w, k_w);
    gemm_all<<<dim3(32, 4, 24), 256>>>(v_b, q_b, k_b, x2, x1, gv2, gv1, gq, gk);
    energy_HW<<<dim3(64, 2, NB), 256>>>(gq, gk, gatt);
    softmax_kernel<<<(NB * HWP) / 8, 256>>>(gatt);
    aggH_mma<<<dim3(8, 32, NB), 256, aggH_smem>>>(gv2, gv1, x2, x1, gatt, gamma, y);
    aggW_mma<<<dim3(NH, 16, NB), 256>>>(gv2, gv1, gatt, gamma, y);
}

// round 8
// speedup vs baseline: 3.5553x; 1.0803x over previous
#include <cuda_runtime.h>
#include <cuda_fp16.h>
#include <cstddef>
#include <cstdint>

// Problem constants
#define NB 8
#define NC 512
#define NH 64
#define NW 64
#define NCQ 64
#define HWP 4096   // NH*NW
#define KDIM 512

// Scratch (statically allocated device globals; no cudaMalloc allowed)
__device__ float  g_q  [NB * NCQ * HWP];
__device__ float  g_k  [NB * NCQ * HWP];
__device__ __half g_v2h[NB * NC  * HWP];   // 32 MB
__device__ __half g_v1h[NB * NC  * HWP];   // 32 MB
__device__ float  g_att [NB * HWP * 128];  // fp32 energies (softmax input)
__device__ __half g_atth[NB * HWP * 128];  // fp16 softmax output

__device__ __forceinline__ uint32_t pack_h2(float a, float b) {
    __half2 h = __floats2half2_rn(a, b);
    return *reinterpret_cast<uint32_t*>(&h);
}

__device__ __forceinline__ void mma_f16(float& d0, float& d1, float& d2, float& d3,
                                        uint32_t a0, uint32_t a1, uint32_t a2, uint32_t a3,
                                        uint32_t b0, uint32_t b1) {
    asm volatile(
        "mma.sync.aligned.m16n8k16.row.col.f32.f16.f16.f32 "
        "{%0,%1,%2,%3}, {%4,%5,%6,%7}, {%8,%9}, {%0,%1,%2,%3};"
        : "+f"(d0), "+f"(d1), "+f"(d2), "+f"(d3)
        : "r"(a0), "r"(a1), "r"(a2), "r"(a3), "r"(b0), "r"(b1));
}

__device__ __forceinline__ void cp_async16(void* smem_dst, const void* gsrc) {
    uint32_t d = (uint32_t)__cvta_generic_to_shared(smem_dst);
    asm volatile("cp.async.cg.shared.global [%0], [%1], 16;\n" :: "r"(d), "l"(gsrc));
}
#define CP_COMMIT() asm volatile("cp.async.commit_group;\n" ::: "memory")
#define CP_WAIT0()  asm volatile("cp.async.wait_group 0;\n" ::: "memory")

// ---------------------------------------------------------------------------
// gemm_all: all projections, fp16 mma. A (weights) packed fp32->half2 in
// registers each k-tile (no preconv launch). B: LDG float4 pairs -> pack ->
// uint4 STS. Double-buffered.
// z<16: v-pair (b=z&7, s=z>>3, m-tile=y), OUTPUT HALF.
// z>=16: fused q+k (b=z-16, y==0 only), output fp32.
// ---------------------------------------------------------------------------
__global__ void __launch_bounds__(256)
gemm_all(const float* __restrict__ vw, const float* __restrict__ vb,
         const float* __restrict__ qw, const float* __restrict__ qb,
         const float* __restrict__ kw, const float* __restrict__ kb,
         const float* __restrict__ x2, const float* __restrict__ x1,
         __half* __restrict__ gv2, __half* __restrict__ gv1,
         float* __restrict__ gq,  float* __restrict__ gk)
{
    constexpr int NKT = KDIM / 32;   // 16 k-tiles of 32

    __shared__ alignas(16) uint32_t As2[2][16][132];
    __shared__ alignas(16) uint32_t Bs2[2][16][136];

    const int t = threadIdx.x;
    const int z = blockIdx.z;
    const bool qkm = (z >= 16);
    if (qkm && blockIdx.y != 0) return;
    const int b = qkm ? (z - 16) : (z & 7);
    const int s = qkm ? 0 : (z >> 3);
    const int m0 = qkm ? 0 : blockIdx.y * 128;
    const int n0 = blockIdx.x * 128;

    const float* Xb = (qkm ? x2 : (s ? x1 : x2)) + (size_t)b * KDIM * HWP + n0;

    const int warp = t >> 5, lane = t & 31;
    const int gid = lane >> 2, tig = lane & 3;
    const int wm = warp >> 1, wn = warp & 1;

    float acc[2][8][4];
    #pragma unroll
    for (int mi = 0; mi < 2; mi++)
        #pragma unroll
        for (int ni = 0; ni < 8; ni++)
            #pragma unroll
            for (int r = 0; r < 4; r++) acc[mi][ni][r] = 0.f;

    float4 pb[2][2];
    float4 pa[4];

    auto loadA = [&](int kt) {
        #pragma unroll
        for (int i = 0; i < 4; i++) {
            int fa = t + i * 256;
            int row = fa >> 3, c4 = fa & 7;
            const float* src;
            if (qkm) {
                src = (row < 64) ? (qw + (size_t)row * KDIM)
                                 : (kw + (size_t)(row - 64) * KDIM);
            } else {
                src = vw + (size_t)(m0 + row) * KDIM;
            }
            pa[i] = *reinterpret_cast<const float4*>(src + kt * 32 + c4 * 4);
        }
    };
    auto storeA = [&](int buf) {
        #pragma unroll
        for (int i = 0; i < 4; i++) {
            int fa = t + i * 256;
            int row = fa >> 3, c4 = fa & 7;
            As2[buf][2 * c4    ][row] = pack_h2(pa[i].x, pa[i].y);
            As2[buf][2 * c4 + 1][row] = pack_h2(pa[i].z, pa[i].w);
        }
    };
    auto loadB = [&](int kt) {
        #pragma unroll
        for (int i = 0; i < 2; i++) {
            int fb = t + i * 256;
            int k2 = fb >> 5, n4 = fb & 31;
            const float* base = Xb + (size_t)(kt * 32 + 2 * k2) * HWP + n4 * 4;
            pb[i][0] = *reinterpret_cast<const float4*>(base);
            pb[i][1] = *reinterpret_cast<const float4*>(base + HWP);
        }
    };
    auto storeB = [&](int buf) {
        #pragma unroll
        for (int i = 0; i < 2; i++) {
            int fb = t + i * 256;
            int k2 = fb >> 5, n4 = fb & 31;
            uint4 u;
            u.x = pack_h2(pb[i][0].x, pb[i][1].x);
            u.y = pack_h2(pb[i][0].y, pb[i][1].y);
            u.z = pack_h2(pb[i][0].z, pb[i][1].z);
            u.w = pack_h2(pb[i][0].w, pb[i][1].w);
            *reinterpret_cast<uint4*>(&Bs2[buf][k2][n4 * 4]) = u;
        }
    };

    loadA(0); storeA(0);
    loadB(0); storeB(0);
    __syncthreads();

    for (int kt = 0; kt < NKT; kt++) {
        const int cur = kt & 1;
        if (kt + 1 < NKT) { loadA(kt + 1); loadB(kt + 1); }

        #pragma unroll
        for (int ks = 0; ks < 2; ks++) {
            const int kr = ks * 8;
            uint32_t af[2][4];
            #pragma unroll
            for (int mi = 0; mi < 2; mi++) {
                int m = wm * 32 + mi * 16;
                af[mi][0] = As2[cur][kr + tig    ][m + gid];
                af[mi][1] = As2[cur][kr + tig    ][m + gid + 8];
                af[mi][2] = As2[cur][kr + tig + 4][m + gid];
                af[mi][3] = As2[cur][kr + tig + 4][m + gid + 8];
            }
            #pragma unroll
            for (int ni = 0; ni < 8; ni++) {
                int n = wn * 64 + ni * 8 + gid;
                uint32_t b0 = Bs2[cur][kr + tig    ][n];
                uint32_t b1 = Bs2[cur][kr + tig + 4][n];
                #pragma unroll
                for (int mi = 0; mi < 2; mi++)
                    mma_f16(acc[mi][ni][0], acc[mi][ni][1], acc[mi][ni][2], acc[mi][ni][3],
                            af[mi][0], af[mi][1], af[mi][2], af[mi][3], b0, b1);
            }
        }

        if (kt + 1 < NKT) {
            __syncthreads();
            storeA(cur ^ 1); storeB(cur ^ 1);
            __syncthreads();
        }
    }

    #pragma unroll
    for (int mi = 0; mi < 2; mi++) {
        int ml = wm * 32 + mi * 16 + gid;
        #pragma unroll
        for (int half = 0; half < 2; half++) {
            int m = m0 + ml + half * 8;
            if (qkm) {
                float bv;
                float* obase;
                if (m < 64) { bv = qb[m];      obase = gq + ((size_t)b * 64 + m)        * HWP; }
                else        { bv = kb[m - 64]; obase = gk + ((size_t)b * 64 + (m - 64)) * HWP; }
                #pragma unroll
                for (int ni = 0; ni < 8; ni++) {
                    int n = n0 + wn * 64 + ni * 8 + tig * 2;
                    float2 o;
                    o.x = acc[mi][ni][half * 2 + 0] + bv;
                    o.y = acc[mi][ni][half * 2 + 1] + bv;
                    *reinterpret_cast<float2*>(obase + n) = o;
                }
            } else {
                float bv = vb[m];
                __half* O = s ? gv1 : gv2;
                __half* obase = O + ((size_t)b * NC + m) * HWP;
                #pragma unroll
                for (int ni = 0; ni < 8; ni++) {
                    int n = n0 + wn * 64 + ni * 8 + tig * 2;
                    *reinterpret_cast<uint32_t*>(obase + n) =
                        pack_h2(acc[mi][ni][half * 2 + 0] + bv,
                                acc[mi][ni][half * 2 + 1] + bv);
                }
            }
        }
    }
}

// ---------------------------------------------------------------------------
// energy_HW: fused energy_H (y==0) and energy_W (y==1), fp32.
// ---------------------------------------------------------------------------
__global__ void energy_HW(const float* __restrict__ q,
                          const float* __restrict__ k,
                          float* __restrict__ att)
{
    __shared__ float Qs[64][65];
    __shared__ float Ks[64][65];
    const int t = threadIdx.x;
    const int b = blockIdx.z;
    const int tx = t & 15, ty = t >> 4;

    if (blockIdx.y == 0) {
        const int w = blockIdx.x;
        #pragma unroll
        for (int i = 0; i < 16; i++) {
            int idx = t + i * 256;
            int c = idx >> 6, h = idx & 63;
            size_t g = ((size_t)(b * NCQ + c) * NH + h) * NW + w;
            Qs[c][h] = q[g];
            Ks[c][h] = k[g];
        }
        __syncthreads();
        float acc[4][4];
        #pragma unroll
        for (int i = 0; i < 4; i++)
            #pragma unroll
            for (int j = 0; j < 4; j++) acc[i][j] = 0.f;
        for (int c = 0; c < 64; c++) {
            float qa[4], kb[4];
            #pragma unroll
            for (int i = 0; i < 4; i++) qa[i] = Qs[c][ty * 4 + i];
            #pragma unroll
            for (int j = 0; j < 4; j++) kb[j] = Ks[c][tx * 4 + j];
            #pragma unroll
            for (int i = 0; i < 4; i++)
                #pragma unroll
                for (int j = 0; j < 4; j++) acc[i][j] += qa[i] * kb[j];
        }
        #pragma unroll
        for (int i = 0; i < 4; i++) {
            int h = ty * 4 + i;
            float4 o = {acc[i][0], acc[i][1], acc[i][2], acc[i][3]};
            *reinterpret_cast<float4*>(&att[((size_t)(b * NH + h) * NW + w) * 128 + tx * 4]) = o;
        }
    } else {
        const int h = blockIdx.x;
        #pragma unroll
        for (int i = 0; i < 16; i++) {
            int idx = t + i * 256;
            int c = idx >> 6, w = idx & 63;
            size_t g = ((size_t)(b * NCQ + c) * NH + h) * NW + w;
            Qs[c][w] = q[g];
            Ks[c][w] = k[g];
        }
        __syncthreads();
        float acc[4][4];
        #pragma unroll
        for (int i = 0; i < 4; i++)
            #pragma unroll
            for (int j = 0; j < 4; j++) acc[i][j] = 0.f;
        for (int c = 0; c < 64; c++) {
            float qa[4], kb[4];
            #pragma unroll
            for (int i = 0; i < 4; i++) qa[i] = Qs[c][ty * 4 + i];
            #pragma unroll
            for (int j = 0; j < 4; j++) kb[j] = Ks[c][tx * 4 + j];
            #pragma unroll
            for (int i = 0; i < 4; i++)
                #pragma unroll
                for (int j = 0; j < 4; j++) acc[i][j] += qa[i] * kb[j];
        }
        #pragma unroll
        for (int i = 0; i < 4; i++) {
            int w = ty * 4 + i;
            float4 o = {acc[i][0], acc[i][1], acc[i][2], acc[i][3]};
            *reinterpret_cast<float4*>(&att[((size_t)(b * NH + h) * NW + w) * 128 + 64 + tx * 4]) = o;
        }
    }
}

// ---------------------------------------------------------------------------
// softmax: fp32 in -> fp16 out.
// ---------------------------------------------------------------------------
__global__ void softmax_kernel(const float* __restrict__ att,
                               __half* __restrict__ atth)
{
    int gwarp = (blockIdx.x * blockDim.x + threadIdx.x) >> 5;
    int lane  = threadIdx.x & 31;
    if (gwarp >= NB * HWP) return;
    const float4* row = reinterpret_cast<const float4*>(att) + (size_t)gwarp * 32;
    float4 v = row[lane];
    float m = fmaxf(fmaxf(v.x, v.y), fmaxf(v.z, v.w));
    #pragma unroll
    for (int o = 16; o > 0; o >>= 1) m = fmaxf(m, __shfl_xor_sync(0xFFFFFFFFu, m, o));
    v.x = __expf(v.x - m); v.y = __expf(v.y - m);
    v.z = __expf(v.z - m); v.w = __expf(v.w - m);
    float s = v.x + v.y + v.z + v.w;
    #pragma unroll
    for (int o = 16; o > 0; o >>= 1) s += __shfl_xor_sync(0xFFFFFFFFu, s, o);
    float r = 1.0f / s;
    uint2 o;
    o.x = pack_h2(v.x * r, v.y * r);
    o.y = pack_h2(v.z * r, v.w * r);
    *(reinterpret_cast<uint2*>(atth + (size_t)gwarp * 128) + lane) = o;
}

// ---------------------------------------------------------------------------
// aggH_f16: H-aggregation + residual, fp16 mma (m16n8k16).
// Block: (wg: 16 w, cs = s*32+cc: 16 c, b). 256 thr = 8 warps (4 h-tiles x 2 c8).
// Vs: 16 w-planes [16 c][36] half2 (k2 = H' pair). attb: 2 x [64 h][36] half2.
// y[b,c,h,w0..15] = x + g * sum_H' V[c,H',w]*att[h,w,H']  (fully coalesced 64B).
// ---------------------------------------------------------------------------
#define AGH_VS_U32   (16 * 16 * 36)          // 9216
#define AGH_AT_U32   (2 * 64 * 36)           // 4608
#define AGH_SMEM     ((AGH_VS_U32 + AGH_AT_U32) * 4)   // 55296 B

__global__ void __launch_bounds__(256)
aggH_f16(const __half* __restrict__ v2, const __half* __restrict__ v1,
         const float* __restrict__ x2, const float* __restrict__ x1,
         const __half* __restrict__ atth, const float* __restrict__ gamma,
         float* __restrict__ y)
{
    extern __shared__ uint32_t sm[];
    uint32_t* Vs  = sm;                       // [w][c][36]
    uint32_t* atb = sm + AGH_VS_U32;          // [2][64][36]

    const int t  = threadIdx.x;
    const int wg = blockIdx.x;                // 0..3
    const int cs = blockIdx.y;                // s*32 + cc
    const int b  = blockIdx.z;
    const int s  = cs >> 5;
    const int cBase = (cs & 31) * 16;
    const int w0 = wg * 16;

    const __half* v = s ? v1 : v2;
    const float*  x = s ? x1 : x2;
    float* yd = y + (size_t)s * NB * NC * HWP;
    const float g = gamma[0];

    auto issue_att = [&](int w, int buf) {
        #pragma unroll
        for (int i = 0; i < 2; i++) {
            int f = t + i * 256;              // 0..511
            int h = f >> 3, q8 = f & 7;
            cp_async16(atb + (size_t)buf * 64 * 36 + h * 36 + q8 * 4,
                       atth + (((size_t)(b * NH + h) * NW) + (w0 + w)) * 128 + q8 * 8);
        }
    };

    issue_att(0, 0); CP_COMMIT();

    // V tile: 16 c x 64 H' x 16 w halves, transposed into 16 w-planes of [c][k2]
    #pragma unroll
    for (int i = 0; i < 2; i++) {
        int p = t + i * 256;                  // 0..511
        int ci = p >> 5, j = p & 31;          // c-local, H' pair
        const __half* src = v + (((size_t)(b * NC + cBase + ci) * NH) + 2 * j) * NW + w0;
        uint4 ra0 = *reinterpret_cast<const uint4*>(src);
        uint4 ra1 = *reinterpret_cast<const uint4*>(src + 8);
        uint4 rb0 = *reinterpret_cast<const uint4*>(src + NW);
        uint4 rb1 = *reinterpret_cast<const uint4*>(src + NW + 8);
        const __half* ha = reinterpret_cast<const __half*>(&ra0);   // w 0..7
        const __half* hb = reinterpret_cast<const __half*>(&rb0);
        const __half* ha2 = reinterpret_cast<const __half*>(&ra1);  // w 8..15
        const __half* hb2 = reinterpret_cast<const __half*>(&rb1);
        #pragma unroll
        for (int w = 0; w < 8; w++) {
            __half2 u = __halves2half2(ha[w], hb[w]);
            Vs[(size_t)w * 16 * 36 + ci * 36 + j] = *reinterpret_cast<uint32_t*>(&u);
            __half2 u2 = __halves2half2(ha2[w], hb2[w]);
            Vs[(size_t)(w + 8) * 16 * 36 + ci * 36 + j] = *reinterpret_cast<uint32_t*>(&u2);
        }
    }
    CP_WAIT0();
    __syncthreads();

    const int warp = t >> 5, lane = t & 31;
    const int gid = lane >> 2, tig = lane & 3;
    const int mi = warp >> 1;        // h-tile (m16)
    const int nh = warp & 1;         // c8 half

    float acc[16][4];
    #pragma unroll
    for (int w = 0; w < 16; w++)
        #pragma unroll
        for (int r = 0; r < 4; r++) acc[w][r] = 0.f;

    for (int w = 0; w < 16; w++) {
        const int cur = w & 1;
        if (w + 1 < 16) { issue_att(w + 1, cur ^ 1); CP_COMMIT(); }

        const uint32_t* Ac = atb + (size_t)cur * 64 * 36;
        const uint32_t* Vw = Vs + (size_t)w * 16 * 36;
        #pragma unroll
        for (int k = 0; k < 4; k++) {
            const int kk2 = k * 8;
            const int m = mi * 16;
            uint32_t a0 = Ac[(m + gid    ) * 36 + kk2 + tig    ];
            uint32_t a1 = Ac[(m + gid + 8) * 36 + kk2 + tig    ];
            uint32_t a2 = Ac[(m + gid    ) * 36 + kk2 + tig + 4];
            uint32_t a3 = Ac[(m + gid + 8) * 36 + kk2 + tig + 4];
            int n = nh * 8 + gid;
            uint32_t b0 = Vw[n * 36 + kk2 + tig    ];
            uint32_t b1 = Vw[n * 36 + kk2 + tig + 4];
            mma_f16(acc[w][0], acc[w][1], acc[w][2], acc[w][3],
                    a0, a1, a2, a3, b0, b1);
        }
        if (w + 1 < 16) { CP_WAIT0(); __syncthreads(); }
    }

    // Epilogue: y[c][h][w0..15] = x + g*acc  (4 float4 per (h,c))
    #pragma unroll
    for (int rh = 0; rh < 2; rh++) {
        #pragma unroll
        for (int cp = 0; cp < 2; cp++) {
            int h = mi * 16 + gid + rh * 8;
            int c = cBase + nh * 8 + tig * 2 + cp;
            size_t base = ((size_t)(b * NC + c) * NH + h) * NW + w0;
            #pragma unroll
            for (int u = 0; u < 4; u++) {
                float4 xv = *reinterpret_cast<const float4*>(x + base + u * 4);
                float4 o;
                o.x = xv.x + g * acc[u * 4 + 0][rh * 2 + cp];
                o.y = xv.y + g * acc[u * 4 + 1][rh * 2 + cp];
                o.z = xv.z + g * acc[u * 4 + 2][rh * 2 + cp];
                o.w = xv.w + g * acc[u * 4 + 3][rh * 2 + cp];
                *reinterpret_cast<float4*>(yd + base + u * 4) = o;
            }
        }
    }
}

// ---------------------------------------------------------------------------
// aggW_f16: W-aggregation (RMW into y), fp16 mma.
// Block: (h, cs = s*8+cc: 64 c, b). 8 warps = 4 w-tiles x 2 c32 halves.
// ---------------------------------------------------------------------------
__global__ void __launch_bounds__(256)
aggW_f16(const __half* __restrict__ v2, const __half* __restrict__ v1,
         const __half* __restrict__ atth, const float* __restrict__ gamma,
         float* __restrict__ y)
{
    __shared__ alignas(16) uint32_t Ast[64 * 36];   // att W-half [w][k2]
    __shared__ alignas(16) uint32_t Vst[64 * 36];   // V rows [c][k2]

    const int t  = threadIdx.x;
    const int h  = blockIdx.x;
    const int cs = blockIdx.y;
    const int b  = blockIdx.z;
    const int s  = cs >> 3;
    const int cBase = (cs & 7) * 64;

    const __half* v = s ? v1 : v2;
    float* yd = y + (size_t)s * NB * NC * HWP;
    const float g = gamma[0];

    #pragma unroll
    for (int i = 0; i < 2; i++) {
        int f = t + i * 256;              // 0..511
        int r = f >> 3, q8 = f & 7;
        cp_async16(Ast + r * 36 + q8 * 4,
                   atth + (((size_t)(b * NH + h) * NW) + r) * 128 + 64 + q8 * 8);
        cp_async16(Vst + r * 36 + q8 * 4,
                   v + (((size_t)(b * NC + cBase + r) * NH) + h) * NW + q8 * 8);
    }
    CP_COMMIT();
    CP_WAIT0();
    __syncthreads();

    const int warp = t >> 5, lane = t & 31;
    const int gid = lane >> 2, tig = lane & 3;
    const int mi = warp >> 1;     // w-tile
    const int nh = warp & 1;      // c32 half

    float acc[4][4];
    #pragma unroll
    for (int ni = 0; ni < 4; ni++)
        #pragma unroll
        for (int r = 0; r < 4; r++) acc[ni][r] = 0.f;

    #pragma unroll
    for (int k = 0; k < 4; k++) {
        const int kk2 = k * 8;
        const int m = mi * 16;
        uint32_t a0 = Ast[(m + gid    ) * 36 + kk2 + tig    ];
        uint32_t a1 = Ast[(m + gid + 8) * 36 + kk2 + tig    ];
        uint32_t a2 = Ast[(m + gid    ) * 36 + kk2 + tig + 4];
        uint32_t a3 = Ast[(m + gid + 8) * 36 + kk2 + tig + 4];
        #pragma unroll
        for (int ni = 0; ni < 4; ni++) {
            int n = nh * 32 + ni * 8 + gid;
            uint32_t b0 = Vst[n * 36 + kk2 + tig    ];
            uint32_t b1 = Vst[n * 36 + kk2 + tig + 4];
            mma_f16(acc[ni][0], acc[ni][1], acc[ni][2], acc[ni][3],
                    a0, a1, a2, a3, b0, b1);
        }
    }

    #pragma unroll
    for (int ni = 0; ni < 4; ni++) {
        #pragma unroll
        for (int rh = 0; rh < 2; rh++) {
            int w = mi * 16 + gid + rh * 8;
            #pragma unroll
            for (int cp = 0; cp < 2; cp++) {
                int c = cBase + nh * 32 + ni * 8 + tig * 2 + cp;
                size_t idx = ((size_t)(b * NC + c) * NH + h) * NW + w;
                yd[idx] += g * acc[ni][rh * 2 + cp];
            }
        }
    }
}

// ---------------------------------------------------------------------------
extern "C" void kernel_launch(void* const* d_in, const int* in_sizes, int n_in,
                              void* d_out, int out_size)
{
    const float* x2    = (const float*)d_in[0];
    const float* x1    = (const float*)d_in[1];
    const float* q_w   = (const float*)d_in[2];
    const float* q_b   = (const float*)d_in[3];
    const float* k_w   = (const float*)d_in[4];
    const float* k_b   = (const float*)d_in[5];
    const float* v_w   = (const float*)d_in[6];
    const float* v_b   = (const float*)d_in[7];
    const float* gamma = (const float*)d_in[8];
    float* y = (float*)d_out;

    float *gq, *gk, *gatt;
    __half *gv2, *gv1, *gatth;
    cudaGetSymbolAddress((void**)&gq,   g_q);
    cudaGetSymbolAddress((void**)&gk,   g_k);
    cudaGetSymbolAddress((void**)&gv2,  g_v2h);
    cudaGetSymbolAddress((void**)&gv1,  g_v1h);
    cudaGetSymbolAddress((void**)&gatt, g_att);
    cudaGetSymbolAddress((void**)&gatth, g_atth);

    cudaFuncSetAttribute(aggH_f16, cudaFuncAttributeMaxDynamicSharedMemorySize, AGH_SMEM);

    // Launch order matters: ncu capture slot = 4th launch = aggH_f16.
    gemm_all<<<dim3(32, 4, 24), 256>>>(v_w, v_b, q_w, q_b, k_w, k_b,
                                       x2, x1, gv2, gv1, gq, gk);
    energy_HW<<<dim3(64, 2, NB), 256>>>(gq, gk, gatt);
    softmax_kernel<<<(NB * HWP) / 8, 256>>>(gatt, gatth);
    aggH_f16<<<dim3(4, 64, NB), 256, AGH_SMEM>>>(gv2, gv1, x2, x1, gatth, gamma, y);
    aggW_f16<<<dim3(NH, 16, NB), 256>>>(gv2, gv1, gatth, gamma, y);
}

// round 9
// speedup vs baseline: 3.6891x; 1.0376x over previous
#include <cuda_runtime.h>
#include <cuda_fp16.h>
#include <cstddef>
#include <cstdint>

// Problem constants
#define NB 8
#define NC 512
#define NH 64
#define NW 64
#define NCQ 64
#define HWP 4096   // NH*NW
#define KDIM 512

// Scratch (statically allocated device globals; no cudaMalloc allowed)
__device__ float  g_q  [NB * NCQ * HWP];
__device__ float  g_k  [NB * NCQ * HWP];
__device__ __half g_v2h[NB * NC  * HWP];   // 32 MB
__device__ __half g_v1h[NB * NC  * HWP];   // 32 MB
__device__ float  g_att [NB * HWP * 128];  // fp32 energies (softmax input)
__device__ __half g_atth[NB * HWP * 128];  // fp16 softmax output

__device__ __forceinline__ uint32_t pack_h2(float a, float b) {
    __half2 h = __floats2half2_rn(a, b);
    return *reinterpret_cast<uint32_t*>(&h);
}

__device__ __forceinline__ void mma_f16(float& d0, float& d1, float& d2, float& d3,
                                        uint32_t a0, uint32_t a1, uint32_t a2, uint32_t a3,
                                        uint32_t b0, uint32_t b1) {
    asm volatile(
        "mma.sync.aligned.m16n8k16.row.col.f32.f16.f16.f32 "
        "{%0,%1,%2,%3}, {%4,%5,%6,%7}, {%8,%9}, {%0,%1,%2,%3};"
        : "+f"(d0), "+f"(d1), "+f"(d2), "+f"(d3)
        : "r"(a0), "r"(a1), "r"(a2), "r"(a3), "r"(b0), "r"(b1));
}

__device__ __forceinline__ void cp_async16(void* smem_dst, const void* gsrc) {
    uint32_t d = (uint32_t)__cvta_generic_to_shared(smem_dst);
    asm volatile("cp.async.cg.shared.global [%0], [%1], 16;\n" :: "r"(d), "l"(gsrc));
}
#define CP_COMMIT() asm volatile("cp.async.commit_group;\n" ::: "memory")
#define CP_WAIT0()  asm volatile("cp.async.wait_group 0;\n" ::: "memory")

// ---------------------------------------------------------------------------
// gemm_all (unchanged from R8): all projections, fp16 mma.
// ---------------------------------------------------------------------------
__global__ void __launch_bounds__(256)
gemm_all(const float* __restrict__ vw, const float* __restrict__ vb,
         const float* __restrict__ qw, const float* __restrict__ qb,
         const float* __restrict__ kw, const float* __restrict__ kb,
         const float* __restrict__ x2, const float* __restrict__ x1,
         __half* __restrict__ gv2, __half* __restrict__ gv1,
         float* __restrict__ gq,  float* __restrict__ gk)
{
    constexpr int NKT = KDIM / 32;

    __shared__ alignas(16) uint32_t As2[2][16][132];
    __shared__ alignas(16) uint32_t Bs2[2][16][136];

    const int t = threadIdx.x;
    const int z = blockIdx.z;
    const bool qkm = (z >= 16);
    if (qkm && blockIdx.y != 0) return;
    const int b = qkm ? (z - 16) : (z & 7);
    const int s = qkm ? 0 : (z >> 3);
    const int m0 = qkm ? 0 : blockIdx.y * 128;
    const int n0 = blockIdx.x * 128;

    const float* Xb = (qkm ? x2 : (s ? x1 : x2)) + (size_t)b * KDIM * HWP + n0;

    const int warp = t >> 5, lane = t & 31;
    const int gid = lane >> 2, tig = lane & 3;
    const int wm = warp >> 1, wn = warp & 1;

    float acc[2][8][4];
    #pragma unroll
    for (int mi = 0; mi < 2; mi++)
        #pragma unroll
        for (int ni = 0; ni < 8; ni++)
            #pragma unroll
            for (int r = 0; r < 4; r++) acc[mi][ni][r] = 0.f;

    float4 pb[2][2];
    float4 pa[4];

    auto loadA = [&](int kt) {
        #pragma unroll
        for (int i = 0; i < 4; i++) {
            int fa = t + i * 256;
            int row = fa >> 3, c4 = fa & 7;
            const float* src;
            if (qkm) {
                src = (row < 64) ? (qw + (size_t)row * KDIM)
                                 : (kw + (size_t)(row - 64) * KDIM);
            } else {
                src = vw + (size_t)(m0 + row) * KDIM;
            }
            pa[i] = *reinterpret_cast<const float4*>(src + kt * 32 + c4 * 4);
        }
    };
    auto storeA = [&](int buf) {
        #pragma unroll
        for (int i = 0; i < 4; i++) {
            int fa = t + i * 256;
            int row = fa >> 3, c4 = fa & 7;
            As2[buf][2 * c4    ][row] = pack_h2(pa[i].x, pa[i].y);
            As2[buf][2 * c4 + 1][row] = pack_h2(pa[i].z, pa[i].w);
        }
    };
    auto loadB = [&](int kt) {
        #pragma unroll
        for (int i = 0; i < 2; i++) {
            int fb = t + i * 256;
            int k2 = fb >> 5, n4 = fb & 31;
            const float* base = Xb + (size_t)(kt * 32 + 2 * k2) * HWP + n4 * 4;
            pb[i][0] = *reinterpret_cast<const float4*>(base);
            pb[i][1] = *reinterpret_cast<const float4*>(base + HWP);
        }
    };
    auto storeB = [&](int buf) {
        #pragma unroll
        for (int i = 0; i < 2; i++) {
            int fb = t + i * 256;
            int k2 = fb >> 5, n4 = fb & 31;
            uint4 u;
            u.x = pack_h2(pb[i][0].x, pb[i][1].x);
            u.y = pack_h2(pb[i][0].y, pb[i][1].y);
            u.z = pack_h2(pb[i][0].z, pb[i][1].z);
            u.w = pack_h2(pb[i][0].w, pb[i][1].w);
            *reinterpret_cast<uint4*>(&Bs2[buf][k2][n4 * 4]) = u;
        }
    };

    loadA(0); storeA(0);
    loadB(0); storeB(0);
    __syncthreads();

    for (int kt = 0; kt < NKT; kt++) {
        const int cur = kt & 1;
        if (kt + 1 < NKT) { loadA(kt + 1); loadB(kt + 1); }

        #pragma unroll
        for (int ks = 0; ks < 2; ks++) {
            const int kr = ks * 8;
            uint32_t af[2][4];
            #pragma unroll
            for (int mi = 0; mi < 2; mi++) {
                int m = wm * 32 + mi * 16;
                af[mi][0] = As2[cur][kr + tig    ][m + gid];
                af[mi][1] = As2[cur][kr + tig    ][m + gid + 8];
                af[mi][2] = As2[cur][kr + tig + 4][m + gid];
                af[mi][3] = As2[cur][kr + tig + 4][m + gid + 8];
            }
            #pragma unroll
            for (int ni = 0; ni < 8; ni++) {
                int n = wn * 64 + ni * 8 + gid;
                uint32_t b0 = Bs2[cur][kr + tig    ][n];
                uint32_t b1 = Bs2[cur][kr + tig + 4][n];
                #pragma unroll
                for (int mi = 0; mi < 2; mi++)
                    mma_f16(acc[mi][ni][0], acc[mi][ni][1], acc[mi][ni][2], acc[mi][ni][3],
                            af[mi][0], af[mi][1], af[mi][2], af[mi][3], b0, b1);
            }
        }

        if (kt + 1 < NKT) {
            __syncthreads();
            storeA(cur ^ 1); storeB(cur ^ 1);
            __syncthreads();
        }
    }

    #pragma unroll
    for (int mi = 0; mi < 2; mi++) {
        int ml = wm * 32 + mi * 16 + gid;
        #pragma unroll
        for (int half = 0; half < 2; half++) {
            int m = m0 + ml + half * 8;
            if (qkm) {
                float bv;
                float* obase;
                if (m < 64) { bv = qb[m];      obase = gq + ((size_t)b * 64 + m)        * HWP; }
                else        { bv = kb[m - 64]; obase = gk + ((size_t)b * 64 + (m - 64)) * HWP; }
                #pragma unroll
                for (int ni = 0; ni < 8; ni++) {
                    int n = n0 + wn * 64 + ni * 8 + tig * 2;
                    float2 o;
                    o.x = acc[mi][ni][half * 2 + 0] + bv;
                    o.y = acc[mi][ni][half * 2 + 1] + bv;
                    *reinterpret_cast<float2*>(obase + n) = o;
                }
            } else {
                float bv = vb[m];
                __half* O = s ? gv1 : gv2;
                __half* obase = O + ((size_t)b * NC + m) * HWP;
                #pragma unroll
                for (int ni = 0; ni < 8; ni++) {
                    int n = n0 + wn * 64 + ni * 8 + tig * 2;
                    *reinterpret_cast<uint32_t*>(obase + n) =
                        pack_h2(acc[mi][ni][half * 2 + 0] + bv,
                                acc[mi][ni][half * 2 + 1] + bv);
                }
            }
        }
    }
}

// ---------------------------------------------------------------------------
// energy_HW (unchanged)
// ---------------------------------------------------------------------------
__global__ void energy_HW(const float* __restrict__ q,
                          const float* __restrict__ k,
                          float* __restrict__ att)
{
    __shared__ float Qs[64][65];
    __shared__ float Ks[64][65];
    const int t = threadIdx.x;
    const int b = blockIdx.z;
    const int tx = t & 15, ty = t >> 4;

    if (blockIdx.y == 0) {
        const int w = blockIdx.x;
        #pragma unroll
        for (int i = 0; i < 16; i++) {
            int idx = t + i * 256;
            int c = idx >> 6, h = idx & 63;
            size_t g = ((size_t)(b * NCQ + c) * NH + h) * NW + w;
            Qs[c][h] = q[g];
            Ks[c][h] = k[g];
        }
        __syncthreads();
        float acc[4][4];
        #pragma unroll
        for (int i = 0; i < 4; i++)
            #pragma unroll
            for (int j = 0; j < 4; j++) acc[i][j] = 0.f;
        for (int c = 0; c < 64; c++) {
            float qa[4], kb[4];
            #pragma unroll
            for (int i = 0; i < 4; i++) qa[i] = Qs[c][ty * 4 + i];
            #pragma unroll
            for (int j = 0; j < 4; j++) kb[j] = Ks[c][tx * 4 + j];
            #pragma unroll
            for (int i = 0; i < 4; i++)
                #pragma unroll
                for (int j = 0; j < 4; j++) acc[i][j] += qa[i] * kb[j];
        }
        #pragma unroll
        for (int i = 0; i < 4; i++) {
            int h = ty * 4 + i;
            float4 o = {acc[i][0], acc[i][1], acc[i][2], acc[i][3]};
            *reinterpret_cast<float4*>(&att[((size_t)(b * NH + h) * NW + w) * 128 + tx * 4]) = o;
        }
    } else {
        const int h = blockIdx.x;
        #pragma unroll
        for (int i = 0; i < 16; i++) {
            int idx = t + i * 256;
            int c = idx >> 6, w = idx & 63;
            size_t g = ((size_t)(b * NCQ + c) * NH + h) * NW + w;
            Qs[c][w] = q[g];
            Ks[c][w] = k[g];
        }
        __syncthreads();
        float acc[4][4];
        #pragma unroll
        for (int i = 0; i < 4; i++)
            #pragma unroll
            for (int j = 0; j < 4; j++) acc[i][j] = 0.f;
        for (int c = 0; c < 64; c++) {
            float qa[4], kb[4];
            #pragma unroll
            for (int i = 0; i < 4; i++) qa[i] = Qs[c][ty * 4 + i];
            #pragma unroll
            for (int j = 0; j < 4; j++) kb[j] = Ks[c][tx * 4 + j];
            #pragma unroll
            for (int i = 0; i < 4; i++)
                #pragma unroll
                for (int j = 0; j < 4; j++) acc[i][j] += qa[i] * kb[j];
        }
        #pragma unroll
        for (int i = 0; i < 4; i++) {
            int w = ty * 4 + i;
            float4 o = {acc[i][0], acc[i][1], acc[i][2], acc[i][3]};
            *reinterpret_cast<float4*>(&att[((size_t)(b * NH + h) * NW + w) * 128 + 64 + tx * 4]) = o;
        }
    }
}

// ---------------------------------------------------------------------------
// softmax: fp32 in -> fp16 out (unchanged)
// ---------------------------------------------------------------------------
__global__ void softmax_kernel(const float* __restrict__ att,
                               __half* __restrict__ atth)
{
    int gwarp = (blockIdx.x * blockDim.x + threadIdx.x) >> 5;
    int lane  = threadIdx.x & 31;
    if (gwarp >= NB * HWP) return;
    const float4* row = reinterpret_cast<const float4*>(att) + (size_t)gwarp * 32;
    float4 v = row[lane];
    float m = fmaxf(fmaxf(v.x, v.y), fmaxf(v.z, v.w));
    #pragma unroll
    for (int o = 16; o > 0; o >>= 1) m = fmaxf(m, __shfl_xor_sync(0xFFFFFFFFu, m, o));
    v.x = __expf(v.x - m); v.y = __expf(v.y - m);
    v.z = __expf(v.z - m); v.w = __expf(v.w - m);
    float s = v.x + v.y + v.z + v.w;
    #pragma unroll
    for (int o = 16; o > 0; o >>= 1) s += __shfl_xor_sync(0xFFFFFFFFu, s, o);
    float r = 1.0f / s;
    uint2 o;
    o.x = pack_h2(v.x * r, v.y * r);
    o.y = pack_h2(v.z * r, v.w * r);
    *(reinterpret_cast<uint2*>(atth + (size_t)gwarp * 128) + lane) = o;
}

// ---------------------------------------------------------------------------
// aggH_f16 v3: single-shot, no inner-loop syncs.
// Block: (wg: 8 w, cs = s*32+cc: 16 c, b). Grid (8, 64, 8).
// Smem (90KB -> 2 blocks/SM): attS [8w][64h][36] u32, Vs [8w][16c][36] u32.
// All att tiles cp.async'd up front; V transposed once; one __syncthreads;
// then 32 straight-line mma per warp; coalesced x+g*out epilogue.
// ---------------------------------------------------------------------------
#define AGH_AT_U32 (8 * 64 * 36)     // 18432
#define AGH_VS_U32 (8 * 16 * 36)     // 4608
#define AGH_SMEM   ((AGH_AT_U32 + AGH_VS_U32) * 4)   // 92160 B

__global__ void __launch_bounds__(256)
aggH_f16(const __half* __restrict__ v2, const __half* __restrict__ v1,
         const float* __restrict__ x2, const float* __restrict__ x1,
         const __half* __restrict__ atth, const float* __restrict__ gamma,
         float* __restrict__ y)
{
    extern __shared__ uint32_t sm[];
    uint32_t* attS = sm;                    // [8][64][36]
    uint32_t* Vs   = sm + AGH_AT_U32;       // [8][16][36]

    const int t  = threadIdx.x;
    const int wg = blockIdx.x;              // 0..7
    const int cs = blockIdx.y;              // s*32 + cc
    const int b  = blockIdx.z;
    const int s  = cs >> 5;
    const int cBase = (cs & 31) * 16;
    const int w0 = wg * 8;

    const __half* v = s ? v1 : v2;
    const float*  x = s ? x1 : x2;
    float* yd = y + (size_t)s * NB * NC * HWP;
    const float g = gamma[0];

    // Issue ALL att tiles: 8 w x 64 h rows x 128B = 4096 16B chunks.
    #pragma unroll
    for (int i = 0; i < 16; i++) {
        int f = t + i * 256;                // 0..4095
        int w = f >> 9;
        int r = f & 511;
        int h = r >> 3, q8 = r & 7;
        cp_async16(attS + (size_t)w * 64 * 36 + h * 36 + q8 * 4,
                   atth + (((size_t)(b * NH + h) * NW) + (w0 + w)) * 128 + q8 * 8);
    }
    CP_COMMIT();

    // V tile transpose: 16c x 32 H'-pairs, 8 w each.
    #pragma unroll
    for (int i = 0; i < 2; i++) {
        int p = t + i * 256;                // 0..511
        int ci = p >> 5, j = p & 31;
        const __half* src = v + (((size_t)(b * NC + cBase + ci) * NH) + 2 * j) * NW + w0;
        uint4 ra = *reinterpret_cast<const uint4*>(src);        // 8 halves, H'=2j
        uint4 rb = *reinterpret_cast<const uint4*>(src + NW);   // 8 halves, H'=2j+1
        const __half* ha = reinterpret_cast<const __half*>(&ra);
        const __half* hb = reinterpret_cast<const __half*>(&rb);
        #pragma unroll
        for (int w = 0; w < 8; w++) {
            __half2 u = __halves2half2(ha[w], hb[w]);
            Vs[(size_t)w * 16 * 36 + ci * 36 + j] = *reinterpret_cast<uint32_t*>(&u);
        }
    }
    CP_WAIT0();
    __syncthreads();

    const int warp = t >> 5, lane = t & 31;
    const int gid = lane >> 2, tig = lane & 3;
    const int mi = warp >> 1;      // h-tile (m16)
    const int nh = warp & 1;       // c8 half

    float acc[8][4];
    #pragma unroll
    for (int w = 0; w < 8; w++)
        #pragma unroll
        for (int r = 0; r < 4; r++) acc[w][r] = 0.f;

    #pragma unroll
    for (int w = 0; w < 8; w++) {
        const uint32_t* Ac = attS + (size_t)w * 64 * 36;
        const uint32_t* Vw = Vs + (size_t)w * 16 * 36;
        #pragma unroll
        for (int k = 0; k < 4; k++) {
            const int kk2 = k * 8;
            const int m = mi * 16;
            uint32_t a0 = Ac[(m + gid    ) * 36 + kk2 + tig    ];
            uint32_t a1 = Ac[(m + gid + 8) * 36 + kk2 + tig    ];
            uint32_t a2 = Ac[(m + gid    ) * 36 + kk2 + tig + 4];
            uint32_t a3 = Ac[(m + gid + 8) * 36 + kk2 + tig + 4];
            int n = nh * 8 + gid;
            uint32_t b0 = Vw[n * 36 + kk2 + tig    ];
            uint32_t b1 = Vw[n * 36 + kk2 + tig + 4];
            mma_f16(acc[w][0], acc[w][1], acc[w][2], acc[w][3],
                    a0, a1, a2, a3, b0, b1);
        }
    }

    // Epilogue: y[c][h][w0..7] = x + g*acc (two float4 per (h,c))
    #pragma unroll
    for (int rh = 0; rh < 2; rh++) {
        #pragma unroll
        for (int cp = 0; cp < 2; cp++) {
            int h = mi * 16 + gid + rh * 8;
            int c = cBase + nh * 8 + tig * 2 + cp;
            size_t base = ((size_t)(b * NC + c) * NH + h) * NW + w0;
            #pragma unroll
            for (int u = 0; u < 2; u++) {
                float4 xv = *reinterpret_cast<const float4*>(x + base + u * 4);
                float4 o;
                o.x = xv.x + g * acc[u * 4 + 0][rh * 2 + cp];
                o.y = xv.y + g * acc[u * 4 + 1][rh * 2 + cp];
                o.z = xv.z + g * acc[u * 4 + 2][rh * 2 + cp];
                o.w = xv.w + g * acc[u * 4 + 3][rh * 2 + cp];
                *reinterpret_cast<float4*>(yd + base + u * 4) = o;
            }
        }
    }
}

// ---------------------------------------------------------------------------
// aggW_f16 v3: c=128 per block (4x work per block vs R8).
// Block: (h, cs = s*4+cc, b). Grid (64, 8, 8). Smem 28KB.
// 8 warps = 4 w-tiles x 2 c64-halves; 32 mma per warp.
// ---------------------------------------------------------------------------
__global__ void __launch_bounds__(256)
aggW_f16(const __half* __restrict__ v2, const __half* __restrict__ v1,
         const __half* __restrict__ atth, const float* __restrict__ gamma,
         float* __restrict__ y)
{
    __shared__ alignas(16) uint32_t Ast[64 * 36];    // att W-half [w][k2]
    __shared__ alignas(16) uint32_t Vst[128 * 36];   // V rows [c][k2]

    const int t  = threadIdx.x;
    const int h  = blockIdx.x;
    const int cs = blockIdx.y;         // s*4 + cc
    const int b  = blockIdx.z;
    const int s  = cs >> 2;
    const int cBase = (cs & 3) * 128;

    const __half* v = s ? v1 : v2;
    float* yd = y + (size_t)s * NB * NC * HWP;
    const float g = gamma[0];

    // Ast: 64 rows x 8 chunks = 512; Vst: 128 rows x 8 = 1024.
    #pragma unroll
    for (int i = 0; i < 2; i++) {
        int f = t + i * 256;
        int r = f >> 3, q8 = f & 7;
        cp_async16(Ast + r * 36 + q8 * 4,
                   atth + (((size_t)(b * NH + h) * NW) + r) * 128 + 64 + q8 * 8);
    }
    #pragma unroll
    for (int i = 0; i < 4; i++) {
        int f = t + i * 256;
        int r = f >> 3, q8 = f & 7;
        cp_async16(Vst + r * 36 + q8 * 4,
                   v + (((size_t)(b * NC + cBase + r) * NH) + h) * NW + q8 * 8);
    }
    CP_COMMIT();
    CP_WAIT0();
    __syncthreads();

    const int warp = t >> 5, lane = t & 31;
    const int gid = lane >> 2, tig = lane & 3;
    const int mi = warp >> 1;     // w-tile
    const int nh = warp & 1;      // c64 half

    float acc[8][4];
    #pragma unroll
    for (int ni = 0; ni < 8; ni++)
        #pragma unroll
        for (int r = 0; r < 4; r++) acc[ni][r] = 0.f;

    #pragma unroll
    for (int k = 0; k < 4; k++) {
        const int kk2 = k * 8;
        const int m = mi * 16;
        uint32_t a0 = Ast[(m + gid    ) * 36 + kk2 + tig    ];
        uint32_t a1 = Ast[(m + gid + 8) * 36 + kk2 + tig    ];
        uint32_t a2 = Ast[(m + gid    ) * 36 + kk2 + tig + 4];
        uint32_t a3 = Ast[(m + gid + 8) * 36 + kk2 + tig + 4];
        #pragma unroll
        for (int ni = 0; ni < 8; ni++) {
            int n = nh * 64 + ni * 8 + gid;
            uint32_t b0 = Vst[n * 36 + kk2 + tig    ];
            uint32_t b1 = Vst[n * 36 + kk2 + tig + 4];
            mma_f16(acc[ni][0], acc[ni][1], acc[ni][2], acc[ni][3],
                    a0, a1, a2, a3, b0, b1);
        }
    }

    #pragma unroll
    for (int ni = 0; ni < 8; ni++) {
        #pragma unroll
        for (int rh = 0; rh < 2; rh++) {
            int w = mi * 16 + gid + rh * 8;
            #pragma unroll
            for (int cp = 0; cp < 2; cp++) {
                int c = cBase + nh * 64 + ni * 8 + tig * 2 + cp;
                size_t idx = ((size_t)(b * NC + c) * NH + h) * NW + w;
                yd[idx] += g * acc[ni][rh * 2 + cp];
            }
        }
    }
}

// ---------------------------------------------------------------------------
extern "C" void kernel_launch(void* const* d_in, const int* in_sizes, int n_in,
                              void* d_out, int out_size)
{
    const float* x2    = (const float*)d_in[0];
    const float* x1    = (const float*)d_in[1];
    const float* q_w   = (const float*)d_in[2];
    const float* q_b   = (const float*)d_in[3];
    const float* k_w   = (const float*)d_in[4];
    const float* k_b   = (const float*)d_in[5];
    const float* v_w   = (const float*)d_in[6];
    const float* v_b   = (const float*)d_in[7];
    const float* gamma = (const float*)d_in[8];
    float* y = (float*)d_out;

    float *gq, *gk, *gatt;
    __half *gv2, *gv1, *gatth;
    cudaGetSymbolAddress((void**)&gq,   g_q);
    cudaGetSymbolAddress((void**)&gk,   g_k);
    cudaGetSymbolAddress((void**)&gv2,  g_v2h);
    cudaGetSymbolAddress((void**)&gv1,  g_v1h);
    cudaGetSymbolAddress((void**)&gatt, g_att);
    cudaGetSymbolAddress((void**)&gatth, g_atth);

    cudaFuncSetAttribute(aggH_f16, cudaFuncAttributeMaxDynamicSharedMemorySize, AGH_SMEM);

    // Launch order: ncu capture slot = 4th launch = aggH_f16 (verify the fix).
    gemm_all<<<dim3(32, 4, 24), 256>>>(v_w, v_b, q_w, q_b, k_w, k_b,
                                       x2, x1, gv2, gv1, gq, gk);
    energy_HW<<<dim3(64, 2, NB), 256>>>(gq, gk, gatt);
    softmax_kernel<<<(NB * HWP) / 8, 256>>>(gatt, gatth);
    aggH_f16<<<dim3(8, 64, NB), 256, AGH_SMEM>>>(gv2, gv1, x2, x1, gatth, gamma, y);
    aggW_f16<<<dim3(NH, 8, NB), 256>>>(gv2, gv1, gatth, gamma, y);
}